// round 3
// baseline (speedup 1.0000x reference)
#include <cuda_runtime.h>
#include <cuda_bf16.h>
#include <cstdint>

// Problem constants (fixed shapes for this problem instance)
constexpr int NN   = 50000;   // nodes
constexpr int NE   = 600000;  // edges
constexpr int FEAT = 256;
constexpr int HID  = 128;
constexpr int CLS  = 32;
constexpr int NLAYERS = 3;

// Scratch (no allocations allowed -> __device__ globals)
__device__ float g_x [NN * HID];     // current node features
__device__ float g_y [NN * HID];     // y = x @ rel_w
__device__ float g_z [NN * HID];     // z = x @ root_w + rel_b, then scatter-accum
__device__ float g_fg[NN * 64];      // [F | G] per node for edge head
__device__ float g_hw[128 * 64];     // packed head weights

// ---------------------------------------------------------------------------
// Generic fp32 GEMM with packed f32x2 FMA.  C[M,N] = A[M,K] @ B[K,N] (+bias)(relu)
// Row-major everywhere. N == BN * gridDim.y exactly (no N guard), M guarded.
// ---------------------------------------------------------------------------
template<int BM, int BN, int BK, int TM, int TN, bool BIAS, bool RELU>
__global__ void __launch_bounds__((BM / TM) * (BN / TN))
gemm_f32(const float* __restrict__ A, const float* __restrict__ B,
         const float* __restrict__ bias, float* __restrict__ C,
         int M, int N, int K)
{
    constexpr int THREADS = (BM / TM) * (BN / TN);
    constexpr int BKV = BK / 4;   // float4 chunks along K for A rows
    constexpr int BNV = BN / 4;   // float4 chunks along N for B rows

    __shared__ float As[BK][BM + 4];   // +4 pad kills transpose-store conflicts
    __shared__ float Bs[BK][BN];

    const int tid  = threadIdx.x;
    const int row0 = blockIdx.x * BM;
    const int col0 = blockIdx.y * BN;

    constexpr int TCOLS = BN / TN;
    const int trow = (tid / TCOLS) * TM;
    const int tcol = (tid % TCOLS) * TN;

    unsigned long long acc[TM][TN / 2];
#pragma unroll
    for (int i = 0; i < TM; i++)
#pragma unroll
        for (int j = 0; j < TN / 2; j++) acc[i][j] = 0ULL;

    for (int k0 = 0; k0 < K; k0 += BK) {
        // ---- load A tile (transposed into smem), zero-pad rows >= M ----
#pragma unroll
        for (int v = 0; v < (BM * BKV) / THREADS; v++) {
            int vid = tid + v * THREADS;
            int ar  = vid / BKV;
            int ak  = (vid % BKV) * 4;
            float4 t = make_float4(0.f, 0.f, 0.f, 0.f);
            int gr = row0 + ar;
            if (gr < M)
                t = *reinterpret_cast<const float4*>(&A[(size_t)gr * K + k0 + ak]);
            As[ak + 0][ar] = t.x;
            As[ak + 1][ar] = t.y;
            As[ak + 2][ar] = t.z;
            As[ak + 3][ar] = t.w;
        }
        // ---- load B tile ----
#pragma unroll
        for (int v = 0; v < (BK * BNV) / THREADS; v++) {
            int vid = tid + v * THREADS;
            int bk  = vid / BNV;
            int bc  = (vid % BNV) * 4;
            *reinterpret_cast<float4*>(&Bs[bk][bc]) =
                *reinterpret_cast<const float4*>(&B[(size_t)(k0 + bk) * N + col0 + bc]);
        }
        __syncthreads();

#pragma unroll
        for (int kk = 0; kk < BK; kk++) {
            float a[TM];
#pragma unroll
            for (int i = 0; i < TM; i += 4) {
                float4 t = *reinterpret_cast<const float4*>(&As[kk][trow + i]);
                a[i] = t.x; a[i + 1] = t.y; a[i + 2] = t.z; a[i + 3] = t.w;
            }
            unsigned long long b2[TN / 2];
#pragma unroll
            for (int j = 0; j < TN / 2; j++)
                b2[j] = *reinterpret_cast<const unsigned long long*>(&Bs[kk][tcol + 2 * j]);
#pragma unroll
            for (int i = 0; i < TM; i++) {
                unsigned long long aa;
                asm("mov.b64 %0, {%1, %1};" : "=l"(aa) : "f"(a[i]));
#pragma unroll
                for (int j = 0; j < TN / 2; j++)
                    asm("fma.rn.f32x2 %0, %1, %2, %0;"
                        : "+l"(acc[i][j]) : "l"(aa), "l"(b2[j]));
            }
        }
        __syncthreads();
    }

    // ---- epilogue ----
#pragma unroll
    for (int i = 0; i < TM; i++) {
        int gr = row0 + trow + i;
        if (gr >= M) continue;
#pragma unroll
        for (int j = 0; j < TN / 2; j++) {
            float lo, hi;
            asm("mov.b64 {%0, %1}, %2;" : "=f"(lo), "=f"(hi) : "l"(acc[i][j]));
            int c = col0 + tcol + 2 * j;
            if (BIAS) { lo += bias[c]; hi += bias[c + 1]; }
            if (RELU) { lo = fmaxf(lo, 0.f); hi = fmaxf(hi, 0.f); }
            C[(size_t)gr * N + c]     = lo;
            C[(size_t)gr * N + c + 1] = hi;
        }
    }
}

// ---------------------------------------------------------------------------
// scatter: z[dst] += y[src]  (warp per edge, float4 gather, scalar REDG adds)
// edge_index is int32 (JAX canonicalizes int64 -> int32 with x64 disabled)
// ---------------------------------------------------------------------------
__global__ void scatter_add_kernel(const float4* __restrict__ y4,
                                   float* __restrict__ z,
                                   const int* __restrict__ ei)
{
    int warp = (blockIdx.x * blockDim.x + threadIdx.x) >> 5;
    int lane = threadIdx.x & 31;
    if (warp >= NE) return;
    int src = ei[warp];
    int dst = ei[NE + warp];
    float4 v = y4[(size_t)src * (HID / 4) + lane];
    float* zp = z + (size_t)dst * HID + lane * 4;
    atomicAdd(zp + 0, v.x);
    atomicAdd(zp + 1, v.y);
    atomicAdd(zp + 2, v.z);
    atomicAdd(zp + 3, v.w);
}

// ---------------------------------------------------------------------------
// x = relu(z)   (vectorized)
// ---------------------------------------------------------------------------
__global__ void relu_copy_kernel(const float4* __restrict__ z4,
                                 float4* __restrict__ x4, int n4)
{
    int i = blockIdx.x * blockDim.x + threadIdx.x;
    if (i >= n4) return;
    float4 t = z4[i];
    t.x = fmaxf(t.x, 0.f); t.y = fmaxf(t.y, 0.f);
    t.z = fmaxf(t.z, 0.f); t.w = fmaxf(t.w, 0.f);
    x4[i] = t;
}

// ---------------------------------------------------------------------------
// pack head_w [256,32] -> [128,64]:  packed[k][c] = W[k][c] (c<32) else W[128+k][c-32]
// ---------------------------------------------------------------------------
__global__ void pack_head_kernel(const float* __restrict__ hw,
                                 float* __restrict__ packed)
{
    int i = blockIdx.x * blockDim.x + threadIdx.x;
    if (i >= 128 * 64) return;
    int k = i / 64, c = i % 64;
    packed[i] = (c < 32) ? hw[k * CLS + c] : hw[(128 + k) * CLS + (c - 32)];
}

// ---------------------------------------------------------------------------
// out[e,c] = FG[src,c] + FG[dst,32+c] + head_b[c]   (warp per edge, lane=class)
// ---------------------------------------------------------------------------
__global__ void edge_out_kernel(const float* __restrict__ fg,
                                const int* __restrict__ ei,
                                const float* __restrict__ head_b,
                                float* __restrict__ out)
{
    int warp = (blockIdx.x * blockDim.x + threadIdx.x) >> 5;
    int lane = threadIdx.x & 31;
    if (warp >= NE) return;
    int src = ei[warp];
    int dst = ei[NE + warp];
    float v = fg[(size_t)src * 64 + lane] + fg[(size_t)dst * 64 + 32 + lane] + head_b[lane];
    out[(size_t)warp * CLS + lane] = v;
}

// ---------------------------------------------------------------------------
extern "C" void kernel_launch(void* const* d_in, const int* in_sizes, int n_in,
                              void* d_out, int out_size)
{
    const float* obj    = (const float*)d_in[0];
    const int*   ei     = (const int*)d_in[1];   // int32 (JAX x64 disabled)
    const float* emb_w  = (const float*)d_in[2];
    const float* emb_b  = (const float*)d_in[3];
    const float* rel_w  = (const float*)d_in[4];
    const float* rel_b  = (const float*)d_in[5];
    const float* root_w = (const float*)d_in[6];
    const float* head_w = (const float*)d_in[7];
    const float* head_b = (const float*)d_in[8];
    float*       out    = (float*)d_out;

    float *x, *y, *z, *fg, *hw;
    cudaGetSymbolAddress((void**)&x,  g_x);
    cudaGetSymbolAddress((void**)&y,  g_y);
    cudaGetSymbolAddress((void**)&z,  g_z);
    cudaGetSymbolAddress((void**)&fg, g_fg);
    cudaGetSymbolAddress((void**)&hw, g_hw);

    const int gemm_gx = (NN + 127) / 128;  // 391
    const dim3 g1(gemm_gx, 1);

    // pack head weights (independent; launch early)
    pack_head_kernel<<<(128 * 64 + 255) / 256, 256>>>(head_w, hw);

    // x = relu(obj @ emb_w + emb_b)   [50000,128], K=256
    gemm_f32<128, 128, 16, 8, 8, true, true><<<g1, 256>>>(
        obj, emb_w, emb_b, x, NN, HID, FEAT);

    const int scatter_blocks = (NE * 32 + 255) / 256;  // 75000
    const int relu_blocks    = (NN * HID / 4 + 255) / 256;

    for (int l = 0; l < NLAYERS; l++) {
        // y = x @ rel_w[l]
        gemm_f32<128, 128, 16, 8, 8, false, false><<<g1, 256>>>(
            x, rel_w + (size_t)l * HID * HID, nullptr, y, NN, HID, HID);
        // z = x @ root_w[l] + rel_b[l]
        gemm_f32<128, 128, 16, 8, 8, true, false><<<g1, 256>>>(
            x, root_w + (size_t)l * HID * HID, rel_b + (size_t)l * HID, z, NN, HID, HID);
        // z[dst] += y[src]
        scatter_add_kernel<<<scatter_blocks, 256>>>((const float4*)y, z, ei);
        // x = relu(z)
        relu_copy_kernel<<<relu_blocks, 256>>>((const float4*)z, (float4*)x, NN * HID / 4);
    }

    // FG = x @ packed_head  [50000, 64]
    gemm_f32<128, 64, 16, 8, 4, false, false><<<g1, 256>>>(
        x, hw, nullptr, fg, NN, 64, HID);

    // out[e] = FG[src, :32] + FG[dst, 32:] + head_b
    edge_out_kernel<<<scatter_blocks, 256>>>(fg, ei, head_b, out);
}

// round 6
// speedup vs baseline: 1.8190x; 1.8190x over previous
#include <cuda_runtime.h>
#include <cuda_bf16.h>
#include <cstdint>

constexpr int NN   = 50000;   // nodes
constexpr int NE   = 600000;  // edges
constexpr int FEAT = 256;
constexpr int HID  = 128;
constexpr int CLS  = 32;
constexpr int NLAYERS = 3;

// Scratch (no allocations allowed -> __device__ globals)
__device__ float g_x [NN * HID];
__device__ float g_y [NN * HID];
__device__ float g_z [NN * HID];
__device__ float g_fg[NN * 64];
__device__ float g_hw[128 * 64];
__device__ int   g_off[NN + 1];
__device__ int   g_cur[NN];
__device__ int   g_csr[NE];

#define FMA2(acc, a, b) asm("fma.rn.f32x2 %0, %1, %2, %0;" : "+l"(acc) : "l"(a), "l"(b))

__device__ __forceinline__ unsigned long long dup_f32(float x) {
    unsigned long long r;
    asm("mov.b64 %0, {%1, %1};" : "=l"(r) : "f"(x));
    return r;
}
__device__ __forceinline__ void unpack2(unsigned long long v, float& lo, float& hi) {
    asm("mov.b64 {%0, %1}, %2;" : "=f"(lo), "=f"(hi) : "l"(v));
}

// ---------------------------------------------------------------------------
// Dual GEMM: [Y | Z] = A[M,128] @ [B1 | B2] (each [128,128] row-major)
// Z gets +bias. BM=128, BN=256(=2x128), BK=16, 512 threads, TM=8, TN=2x4.
// Register-staged double buffering.
// ---------------------------------------------------------------------------
__global__ void __launch_bounds__(512)
gemm_dual(const float* __restrict__ A, const float* __restrict__ B1,
          const float* __restrict__ B2, const float* __restrict__ bias,
          float* __restrict__ Y, float* __restrict__ Z, int M)
{
    __shared__ float As[16][128 + 4];
    __shared__ float Bs[16][256];

    const int tid  = threadIdx.x;
    const int row0 = blockIdx.x * 128;
    const int trow = (tid >> 5) * 8;        // 16 row groups
    const int tcol = (tid & 31) * 4;        // 32 col groups (4-wide, + twin at +128)

    const int ar = tid >> 2;                // A stage: 128 rows x 4 k-chunks
    const int ak = (tid & 3) * 4;

    unsigned long long accY[8][2], accZ[8][2];
#pragma unroll
    for (int i = 0; i < 8; i++) {
        accY[i][0] = accY[i][1] = 0ULL;
        accZ[i][0] = accZ[i][1] = 0ULL;
    }

    float4 ra, rb0, rb1;
    {
        int gr = row0 + ar;
        ra = (gr < M) ? *(const float4*)&A[(size_t)gr * 128 + ak]
                      : make_float4(0.f, 0.f, 0.f, 0.f);
        int bk0 = tid >> 6, c0 = (tid & 63) * 4;
        rb0 = (c0 < 128) ? *(const float4*)&B1[bk0 * 128 + c0]
                         : *(const float4*)&B2[bk0 * 128 + c0 - 128];
        int v1 = tid + 512;
        int bk1 = v1 >> 6, c1 = (v1 & 63) * 4;
        rb1 = (c1 < 128) ? *(const float4*)&B1[bk1 * 128 + c1]
                         : *(const float4*)&B2[bk1 * 128 + c1 - 128];
    }

    for (int it = 0; it < 8; it++) {
        As[ak + 0][ar] = ra.x; As[ak + 1][ar] = ra.y;
        As[ak + 2][ar] = ra.z; As[ak + 3][ar] = ra.w;
        { int bk = tid >> 6, c = (tid & 63) * 4; *(float4*)&Bs[bk][c] = rb0; }
        { int v = tid + 512; int bk = v >> 6, c = (v & 63) * 4; *(float4*)&Bs[bk][c] = rb1; }
        __syncthreads();

        if (it < 7) {
            int k0 = (it + 1) * 16;
            int gr = row0 + ar;
            ra = (gr < M) ? *(const float4*)&A[(size_t)gr * 128 + k0 + ak]
                          : make_float4(0.f, 0.f, 0.f, 0.f);
            int bk0 = tid >> 6, c0 = (tid & 63) * 4;
            rb0 = (c0 < 128) ? *(const float4*)&B1[(k0 + bk0) * 128 + c0]
                             : *(const float4*)&B2[(k0 + bk0) * 128 + c0 - 128];
            int v1 = tid + 512;
            int bk1 = v1 >> 6, c1 = (v1 & 63) * 4;
            rb1 = (c1 < 128) ? *(const float4*)&B1[(k0 + bk1) * 128 + c1]
                             : *(const float4*)&B2[(k0 + bk1) * 128 + c1 - 128];
        }

#pragma unroll
        for (int kk = 0; kk < 16; kk++) {
            float a[8];
            *(float4*)&a[0] = *(const float4*)&As[kk][trow];
            *(float4*)&a[4] = *(const float4*)&As[kk][trow + 4];
            float4 by = *(const float4*)&Bs[kk][tcol];
            float4 bz = *(const float4*)&Bs[kk][tcol + 128];
            unsigned long long by01 = ((const unsigned long long*)&by)[0];
            unsigned long long by23 = ((const unsigned long long*)&by)[1];
            unsigned long long bz01 = ((const unsigned long long*)&bz)[0];
            unsigned long long bz23 = ((const unsigned long long*)&bz)[1];
#pragma unroll
            for (int i = 0; i < 8; i++) {
                unsigned long long aa = dup_f32(a[i]);
                FMA2(accY[i][0], aa, by01);
                FMA2(accY[i][1], aa, by23);
                FMA2(accZ[i][0], aa, bz01);
                FMA2(accZ[i][1], aa, bz23);
            }
        }
        __syncthreads();
    }

    float b0 = bias[tcol], b1 = bias[tcol + 1], b2 = bias[tcol + 2], b3 = bias[tcol + 3];
#pragma unroll
    for (int i = 0; i < 8; i++) {
        int gr = row0 + trow + i;
        if (gr >= M) continue;
        float lo, hi;
        unpack2(accY[i][0], lo, hi);
        Y[(size_t)gr * 128 + tcol]     = lo;
        Y[(size_t)gr * 128 + tcol + 1] = hi;
        unpack2(accY[i][1], lo, hi);
        Y[(size_t)gr * 128 + tcol + 2] = lo;
        Y[(size_t)gr * 128 + tcol + 3] = hi;
        unpack2(accZ[i][0], lo, hi);
        Z[(size_t)gr * 128 + tcol]     = lo + b0;
        Z[(size_t)gr * 128 + tcol + 1] = hi + b1;
        unpack2(accZ[i][1], lo, hi);
        Z[(size_t)gr * 128 + tcol + 2] = lo + b2;
        Z[(size_t)gr * 128 + tcol + 3] = hi + b3;
    }
}

// ---------------------------------------------------------------------------
// Embedding GEMM: X = relu(A[M,256] @ B[256,128] + bias)
// BM=128, BN=128, BK=16, 256 threads, TM=8, TN=2x4, double buffered.
// ---------------------------------------------------------------------------
__global__ void __launch_bounds__(256)
gemm_emb(const float* __restrict__ A, const float* __restrict__ B,
         const float* __restrict__ bias, float* __restrict__ X, int M)
{
    __shared__ float As[16][128 + 4];
    __shared__ float Bs[16][128];

    const int tid  = threadIdx.x;
    const int row0 = blockIdx.x * 128;
    const int trow = (tid >> 4) * 8;        // 16 row groups
    const int tc1  = (tid & 15) * 4;        // cols [tc1..tc1+3], twin at +64

    unsigned long long acc[8][4];
#pragma unroll
    for (int i = 0; i < 8; i++)
#pragma unroll
        for (int j = 0; j < 4; j++) acc[i][j] = 0ULL;

    float4 ra0, ra1, rb0, rb1;
    auto loadA = [&](int k0, int v) -> float4 {
        int vid = tid + v * 256;
        int r = vid >> 2, k = (vid & 3) * 4;
        int gr = row0 + r;
        return (gr < M) ? *(const float4*)&A[(size_t)gr * 256 + k0 + k]
                        : make_float4(0.f, 0.f, 0.f, 0.f);
    };
    auto loadB = [&](int k0, int v) -> float4 {
        int vid = tid + v * 256;
        int bk = vid >> 5, c = (vid & 31) * 4;
        return *(const float4*)&B[(k0 + bk) * 128 + c];
    };

    ra0 = loadA(0, 0); ra1 = loadA(0, 1);
    rb0 = loadB(0, 0); rb1 = loadB(0, 1);

    for (int it = 0; it < 16; it++) {
        {
            int vid = tid; int r = vid >> 2, k = (vid & 3) * 4;
            As[k + 0][r] = ra0.x; As[k + 1][r] = ra0.y; As[k + 2][r] = ra0.z; As[k + 3][r] = ra0.w;
            vid = tid + 256; r = vid >> 2; k = (vid & 3) * 4;
            As[k + 0][r] = ra1.x; As[k + 1][r] = ra1.y; As[k + 2][r] = ra1.z; As[k + 3][r] = ra1.w;
            vid = tid; int bk = vid >> 5, c = (vid & 31) * 4;
            *(float4*)&Bs[bk][c] = rb0;
            vid = tid + 256; bk = vid >> 5; c = (vid & 31) * 4;
            *(float4*)&Bs[bk][c] = rb1;
        }
        __syncthreads();

        if (it < 15) {
            int k0 = (it + 1) * 16;
            ra0 = loadA(k0, 0); ra1 = loadA(k0, 1);
            rb0 = loadB(k0, 0); rb1 = loadB(k0, 1);
        }

#pragma unroll
        for (int kk = 0; kk < 16; kk++) {
            float a[8];
            *(float4*)&a[0] = *(const float4*)&As[kk][trow];
            *(float4*)&a[4] = *(const float4*)&As[kk][trow + 4];
            float4 bA = *(const float4*)&Bs[kk][tc1];
            float4 bB = *(const float4*)&Bs[kk][tc1 + 64];
            unsigned long long bA01 = ((const unsigned long long*)&bA)[0];
            unsigned long long bA23 = ((const unsigned long long*)&bA)[1];
            unsigned long long bB01 = ((const unsigned long long*)&bB)[0];
            unsigned long long bB23 = ((const unsigned long long*)&bB)[1];
#pragma unroll
            for (int i = 0; i < 8; i++) {
                unsigned long long aa = dup_f32(a[i]);
                FMA2(acc[i][0], aa, bA01);
                FMA2(acc[i][1], aa, bA23);
                FMA2(acc[i][2], aa, bB01);
                FMA2(acc[i][3], aa, bB23);
            }
        }
        __syncthreads();
    }

#pragma unroll
    for (int i = 0; i < 8; i++) {
        int gr = row0 + trow + i;
        if (gr >= M) continue;
#pragma unroll
        for (int j = 0; j < 4; j++) {
            int c = (j < 2) ? (tc1 + 2 * j) : (tc1 + 64 + 2 * (j - 2));
            float lo, hi;
            unpack2(acc[i][j], lo, hi);
            lo = fmaxf(lo + bias[c], 0.f);
            hi = fmaxf(hi + bias[c + 1], 0.f);
            X[(size_t)gr * 128 + c]     = lo;
            X[(size_t)gr * 128 + c + 1] = hi;
        }
    }
}

// ---------------------------------------------------------------------------
// Head GEMM (generic, single-buffered): C[M,N] = A[M,K] @ B[K,N]
// ---------------------------------------------------------------------------
template<int BM, int BN, int BK, int TM, int TN>
__global__ void __launch_bounds__((BM / TM) * (BN / TN))
gemm_small(const float* __restrict__ A, const float* __restrict__ B,
           float* __restrict__ C, int M, int N, int K)
{
    constexpr int THREADS = (BM / TM) * (BN / TN);
    constexpr int BKV = BK / 4;
    constexpr int BNV = BN / 4;

    __shared__ float As[BK][BM + 4];
    __shared__ float Bs[BK][BN];

    const int tid  = threadIdx.x;
    const int row0 = blockIdx.x * BM;
    constexpr int TCOLS = BN / TN;
    const int trow = (tid / TCOLS) * TM;
    const int tcol = (tid % TCOLS) * TN;

    unsigned long long acc[TM][TN / 2];
#pragma unroll
    for (int i = 0; i < TM; i++)
#pragma unroll
        for (int j = 0; j < TN / 2; j++) acc[i][j] = 0ULL;

    for (int k0 = 0; k0 < K; k0 += BK) {
#pragma unroll
        for (int v = 0; v < (BM * BKV) / THREADS; v++) {
            int vid = tid + v * THREADS;
            int r = vid / BKV, k = (vid % BKV) * 4;
            float4 t = make_float4(0.f, 0.f, 0.f, 0.f);
            int gr = row0 + r;
            if (gr < M) t = *(const float4*)&A[(size_t)gr * K + k0 + k];
            As[k + 0][r] = t.x; As[k + 1][r] = t.y; As[k + 2][r] = t.z; As[k + 3][r] = t.w;
        }
#pragma unroll
        for (int v = 0; v < (BK * BNV) / THREADS; v++) {
            int vid = tid + v * THREADS;
            int bk = vid / BNV, c = (vid % BNV) * 4;
            *(float4*)&Bs[bk][c] = *(const float4*)&B[(size_t)(k0 + bk) * N + c];
        }
        __syncthreads();

#pragma unroll
        for (int kk = 0; kk < BK; kk++) {
            float a[TM];
#pragma unroll
            for (int i = 0; i < TM; i += 4) {
                float4 t = *(const float4*)&As[kk][trow + i];
                a[i] = t.x; a[i + 1] = t.y; a[i + 2] = t.z; a[i + 3] = t.w;
            }
            unsigned long long b2[TN / 2];
#pragma unroll
            for (int j = 0; j < TN / 2; j++)
                b2[j] = *(const unsigned long long*)&Bs[kk][tcol + 2 * j];
#pragma unroll
            for (int i = 0; i < TM; i++) {
                unsigned long long aa = dup_f32(a[i]);
#pragma unroll
                for (int j = 0; j < TN / 2; j++) FMA2(acc[i][j], aa, b2[j]);
            }
        }
        __syncthreads();
    }

#pragma unroll
    for (int i = 0; i < TM; i++) {
        int gr = row0 + trow + i;
        if (gr >= M) continue;
#pragma unroll
        for (int j = 0; j < TN / 2; j++) {
            float lo, hi;
            unpack2(acc[i][j], lo, hi);
            C[(size_t)gr * N + tcol + 2 * j]     = lo;
            C[(size_t)gr * N + tcol + 2 * j + 1] = hi;
        }
    }
}

// ---------------------------------------------------------------------------
// CSR construction
// ---------------------------------------------------------------------------
__global__ void zero_off_kernel(int* __restrict__ off)
{
    int i = blockIdx.x * blockDim.x + threadIdx.x;
    if (i <= NN) off[i] = 0;
}

__global__ void hist_kernel(const int* __restrict__ ei, int* __restrict__ off)
{
    int e = blockIdx.x * blockDim.x + threadIdx.x;
    if (e >= NE) return;
    atomicAdd(&off[ei[NE + e] + 1], 1);
}

__global__ void __launch_bounds__(1024)
scan_kernel(int* __restrict__ off, int* __restrict__ cur)
{
    __shared__ int part[1024];
    const int tid = threadIdx.x;
    const int chunk = (NN + 1023) / 1024;
    int start = 1 + tid * chunk;
    int end = start + chunk; if (end > NN + 1) end = NN + 1;

    int s = 0;
    for (int i = start; i < end; i++) s += off[i];
    part[tid] = s;
    __syncthreads();
    for (int d = 1; d < 1024; d <<= 1) {
        int v = (tid >= d) ? part[tid - d] : 0;
        __syncthreads();
        part[tid] += v;
        __syncthreads();
    }
    int run = (tid == 0) ? 0 : part[tid - 1];
    for (int i = start; i < end; i++) { run += off[i]; off[i] = run; }
    __syncthreads();
    for (int i = tid; i < NN; i += 1024) cur[i] = off[i];
}

__global__ void fill_kernel(const int* __restrict__ ei, int* __restrict__ cur,
                            int* __restrict__ csr)
{
    int e = blockIdx.x * blockDim.x + threadIdx.x;
    if (e >= NE) return;
    int src = ei[e];
    int dst = ei[NE + e];
    int p = atomicAdd(&cur[dst], 1);
    csr[p] = src;
}

// ---------------------------------------------------------------------------
// Aggregate: x[n] = relu(z[n] + sum_{e in csr[n]} y[src_e])  (warp per node)
// ---------------------------------------------------------------------------
__global__ void aggregate_kernel(const float4* __restrict__ y4,
                                 const float4* __restrict__ z4,
                                 float4* __restrict__ x4,
                                 const int* __restrict__ off,
                                 const int* __restrict__ csr)
{
    int node = (blockIdx.x * blockDim.x + threadIdx.x) >> 5;
    int lane = threadIdx.x & 31;
    if (node >= NN) return;
    int s = off[node], e = off[node + 1];
    float4 acc = z4[(size_t)node * 32 + lane];
    for (int b = s; b < e; b += 32) {
        int idx = b + lane;
        int mysrc = (idx < e) ? csr[idx] : 0;
        int cnt = e - b; if (cnt > 32) cnt = 32;
        for (int j = 0; j < cnt; j++) {
            int src = __shfl_sync(0xffffffffu, mysrc, j);
            float4 v = y4[(size_t)src * 32 + lane];
            acc.x += v.x; acc.y += v.y; acc.z += v.z; acc.w += v.w;
        }
    }
    acc.x = fmaxf(acc.x, 0.f); acc.y = fmaxf(acc.y, 0.f);
    acc.z = fmaxf(acc.z, 0.f); acc.w = fmaxf(acc.w, 0.f);
    x4[(size_t)node * 32 + lane] = acc;
}

// ---------------------------------------------------------------------------
// pack head_w [256,32] -> [128,64]
// ---------------------------------------------------------------------------
__global__ void pack_head_kernel(const float* __restrict__ hw,
                                 float* __restrict__ packed)
{
    int i = blockIdx.x * blockDim.x + threadIdx.x;
    if (i >= 128 * 64) return;
    int k = i / 64, c = i % 64;
    packed[i] = (c < 32) ? hw[k * CLS + c] : hw[(128 + k) * CLS + (c - 32)];
}

// ---------------------------------------------------------------------------
// out[e,c] = FG[src,c] + FG[dst,32+c] + head_b[c]
// ---------------------------------------------------------------------------
__global__ void edge_out_kernel(const float* __restrict__ fg,
                                const int* __restrict__ ei,
                                const float* __restrict__ head_b,
                                float* __restrict__ out)
{
    int warp = (blockIdx.x * blockDim.x + threadIdx.x) >> 5;
    int lane = threadIdx.x & 31;
    if (warp >= NE) return;
    int src = ei[warp];
    int dst = ei[NE + warp];
    float v = fg[(size_t)src * 64 + lane] + fg[(size_t)dst * 64 + 32 + lane] + head_b[lane];
    out[(size_t)warp * CLS + lane] = v;
}

// ---------------------------------------------------------------------------
extern "C" void kernel_launch(void* const* d_in, const int* in_sizes, int n_in,
                              void* d_out, int out_size)
{
    const float* obj    = (const float*)d_in[0];
    const int*   ei     = (const int*)d_in[1];   // int32 (JAX x64 disabled)
    const float* emb_w  = (const float*)d_in[2];
    const float* emb_b  = (const float*)d_in[3];
    const float* rel_w  = (const float*)d_in[4];
    const float* rel_b  = (const float*)d_in[5];
    const float* root_w = (const float*)d_in[6];
    const float* head_w = (const float*)d_in[7];
    const float* head_b = (const float*)d_in[8];
    float*       out    = (float*)d_out;

    float *x, *y, *z, *fg, *hw;
    int *off, *cur, *csr;
    cudaGetSymbolAddress((void**)&x,   g_x);
    cudaGetSymbolAddress((void**)&y,   g_y);
    cudaGetSymbolAddress((void**)&z,   g_z);
    cudaGetSymbolAddress((void**)&fg,  g_fg);
    cudaGetSymbolAddress((void**)&hw,  g_hw);
    cudaGetSymbolAddress((void**)&off, g_off);
    cudaGetSymbolAddress((void**)&cur, g_cur);
    cudaGetSymbolAddress((void**)&csr, g_csr);

    const int gemm_gx = (NN + 127) / 128;       // 391
    const int ne_blocks = (NE + 255) / 256;
    const int warp_blocks = (NE * 32 + 255) / 256;
    const int agg_blocks  = (NN * 32 + 255) / 256;

    // --- CSR build (independent of GEMM chain) ---
    zero_off_kernel<<<(NN + 256) / 256, 256>>>(off);
    hist_kernel<<<ne_blocks, 256>>>(ei, off);
    scan_kernel<<<1, 1024>>>(off, cur);
    fill_kernel<<<ne_blocks, 256>>>(ei, cur, csr);

    // --- head weight pack ---
    pack_head_kernel<<<(128 * 64 + 255) / 256, 256>>>(head_w, hw);

    // --- x = relu(obj @ emb_w + emb_b) ---
    gemm_emb<<<gemm_gx, 256>>>(obj, emb_w, emb_b, x, NN);

    // --- 3 GraphConv layers ---
    for (int l = 0; l < NLAYERS; l++) {
        gemm_dual<<<gemm_gx, 512>>>(x, rel_w + (size_t)l * HID * HID,
                                    root_w + (size_t)l * HID * HID,
                                    rel_b + (size_t)l * HID, y, z, NN);
        aggregate_kernel<<<agg_blocks, 256>>>((const float4*)y, (const float4*)z,
                                              (float4*)x, off, csr);
    }

    // --- edge head ---
    gemm_small<128, 64, 16, 8, 4><<<gemm_gx, 256>>>(x, hw, fg, NN, 64, HID);
    edge_out_kernel<<<warp_blocks, 256>>>(fg, ei, head_b, out);
}

// round 8
// speedup vs baseline: 2.3600x; 1.2974x over previous
#include <cuda_runtime.h>
#include <cuda_bf16.h>
#include <cstdint>

constexpr int NN   = 50000;   // nodes
constexpr int NE   = 600000;  // edges
constexpr int FEAT = 256;
constexpr int HID  = 128;
constexpr int CLS  = 32;
constexpr int NLAYERS = 3;

// ---------------- device scratch (no allocs allowed) ----------------
__device__ float g_x [NN * HID];          // fp32 node features (final layer)
__device__ float g_y [NN * HID];          // y = x @ rel_w
__device__ float g_z [NN * HID];          // z = x @ root_w + b
__device__ float g_fg[NN * 64];
__device__ float g_hw[128 * 64];
__device__ int   g_off[NN + 1];
__device__ int   g_cur[NN];
__device__ int   g_csr[NE];

__device__ __nv_bfloat16 g_xh[NN * HID];   // split x (hi)
__device__ __nv_bfloat16 g_xl[NN * HID];   // split x (lo)
__device__ __nv_bfloat16 g_oh[NN * FEAT];  // split obj
__device__ __nv_bfloat16 g_ol[NN * FEAT];
__device__ __nv_bfloat16 g_ewh[128 * 256]; // emb_w^T hi  [N=128, K=256]
__device__ __nv_bfloat16 g_ewl[128 * 256];
__device__ __nv_bfloat16 g_rwh[3 * 128 * 128]; // rel_w^T
__device__ __nv_bfloat16 g_rwl[3 * 128 * 128];
__device__ __nv_bfloat16 g_owh[3 * 128 * 128]; // root_w^T
__device__ __nv_bfloat16 g_owl[3 * 128 * 128];

// ---------------- helpers ----------------
__device__ __forceinline__ uint32_t smem_u32(const void* p) {
    uint32_t a;
    asm("{ .reg .u64 t; cvta.to.shared.u64 t, %1; cvt.u32.u64 %0, t; }" : "=r"(a) : "l"(p));
    return a;
}
__device__ __forceinline__ void split2(float v, __nv_bfloat16& h, __nv_bfloat16& l) {
    h = __float2bfloat16_rn(v);
    l = __float2bfloat16_rn(v - __bfloat162float(h));
}
__device__ __forceinline__ void ldsm4(uint32_t* r, uint32_t addr) {
    asm volatile("ldmatrix.sync.aligned.m8n8.x4.shared.b16 {%0,%1,%2,%3}, [%4];"
        : "=r"(r[0]), "=r"(r[1]), "=r"(r[2]), "=r"(r[3]) : "r"(addr));
}
__device__ __forceinline__ void ldsm2(uint32_t* r, uint32_t addr) {
    asm volatile("ldmatrix.sync.aligned.m8n8.x2.shared.b16 {%0,%1}, [%2];"
        : "=r"(r[0]), "=r"(r[1]) : "r"(addr));
}
__device__ __forceinline__ void mma_bf16(float* c, const uint32_t* a, const uint32_t* b) {
    asm volatile(
        "mma.sync.aligned.m16n8k16.row.col.f32.bf16.bf16.f32 "
        "{%0,%1,%2,%3}, {%4,%5,%6,%7}, {%8,%9}, {%0,%1,%2,%3};"
        : "+f"(c[0]), "+f"(c[1]), "+f"(c[2]), "+f"(c[3])
        : "r"(a[0]), "r"(a[1]), "r"(a[2]), "r"(a[3]), "r"(b[0]), "r"(b[1]));
}

// ---------------------------------------------------------------------------
// Tensor-core GEMM (split-precision bf16, fp32 accumulate):
//   C[128-tile, 128] = (Ah+Al)[*,K] @ (Bh+Bl)^T   (B given as [N=128, K])
// 3 passes: Ah*Bh + Al*Bh + Ah*Bl.  K chunked at 128.
// mode 0: outF = acc          (Y)
// mode 1: outF = acc + bias   (Z)
// mode 2: split(relu(acc + bias)) -> outH, outL   (embedding)
// ---------------------------------------------------------------------------
constexpr int KCH  = 128;
constexpr int KST  = KCH + 8;                 // padded stride (bf16), 272 bytes
constexpr int TILE_BYTES = 128 * KST * 2;     // 34816
constexpr int GSM_SIZE   = 4 * TILE_BYTES;    // 139264

__global__ void __launch_bounds__(256)
gemm_mma(const __nv_bfloat16* __restrict__ Ah, const __nv_bfloat16* __restrict__ Al,
         const __nv_bfloat16* __restrict__ Bh, const __nv_bfloat16* __restrict__ Bl,
         const float* __restrict__ bias, float* __restrict__ outF,
         __nv_bfloat16* __restrict__ outH, __nv_bfloat16* __restrict__ outL,
         int K, int mode)
{
    extern __shared__ __nv_bfloat16 sm[];
    __nv_bfloat16* sAh = sm;
    __nv_bfloat16* sAl = sm + 128 * KST;
    __nv_bfloat16* sBh = sm + 2 * 128 * KST;
    __nv_bfloat16* sBl = sm + 3 * 128 * KST;

    const int tid  = threadIdx.x;
    const int warp = tid >> 5, lane = tid & 31;
    const int row0 = blockIdx.x * 128;
    const int rows = NN - row0;               // valid rows in this tile
    const int wm = (warp >> 1) * 32;          // warp row offset (4 groups of 32)
    const int wn = (warp & 1) * 64;           // warp col offset (2 groups of 64)

    float acc[2][8][4];
#pragma unroll
    for (int m = 0; m < 2; m++)
#pragma unroll
        for (int nt = 0; nt < 8; nt++)
#pragma unroll
            for (int j = 0; j < 4; j++) acc[m][nt][j] = 0.f;

    const uint32_t uAh = smem_u32(sAh), uAl = smem_u32(sAl);
    const uint32_t uBh = smem_u32(sBh), uBl = smem_u32(sBl);

    // per-lane ldmatrix address components
    const int rin  = lane & 7;
    const int quad = lane >> 3;
    const int a_radd = (quad & 1) * 8 + rin;      // row add within m16 tile
    const int a_cadd = (quad >> 1) * 16;          // byte col add
    const int b_l16  = lane & 15;
    const int b_radd = b_l16 & 7;
    const int b_cadd = (b_l16 >> 3) * 16;

    for (int kc = 0; kc < K; kc += KCH) {
        if (kc) __syncthreads();
        // ---- stage A (hi, lo): 128 rows x 128 bf16, uint4 lanes ----
#pragma unroll
        for (int v = 0; v < 8; v++) {
            int i = tid + v * 256;
            int r = i >> 4, c = (i & 15) * 8;
            uint4 t = make_uint4(0u, 0u, 0u, 0u);
            uint4 u = make_uint4(0u, 0u, 0u, 0u);
            if (r < rows) {
                t = *(const uint4*)(Ah + (size_t)(row0 + r) * K + kc + c);
                u = *(const uint4*)(Al + (size_t)(row0 + r) * K + kc + c);
            }
            *(uint4*)(sAh + r * KST + c) = t;
            *(uint4*)(sAl + r * KST + c) = u;
        }
        // ---- stage B (hi, lo): 128 n-rows x 128 bf16 ----
#pragma unroll
        for (int v = 0; v < 8; v++) {
            int i = tid + v * 256;
            int r = i >> 4, c = (i & 15) * 8;
            *(uint4*)(sBh + r * KST + c) = *(const uint4*)(Bh + (size_t)r * K + kc + c);
            *(uint4*)(sBl + r * KST + c) = *(const uint4*)(Bl + (size_t)r * K + kc + c);
        }
        __syncthreads();

        // ---- compute: 8 k-steps of 16 ----
#pragma unroll
        for (int ks = 0; ks < 8; ks++) {
            uint32_t afh[2][4], afl[2][4];
#pragma unroll
            for (int m = 0; m < 2; m++) {
                uint32_t off = (uint32_t)(wm + m * 16 + a_radd) * (KST * 2)
                             + (uint32_t)(ks * 32 + a_cadd);
                ldsm4(afh[m], uAh + off);
                ldsm4(afl[m], uAl + off);
            }
#pragma unroll
            for (int nt = 0; nt < 8; nt++) {
                uint32_t bh[2], bl[2];
                uint32_t off = (uint32_t)(wn + nt * 8 + b_radd) * (KST * 2)
                             + (uint32_t)(ks * 32 + b_cadd);
                ldsm2(bh, uBh + off);
                ldsm2(bl, uBl + off);
#pragma unroll
                for (int m = 0; m < 2; m++) {
                    mma_bf16(acc[m][nt], afh[m], bh);
                    mma_bf16(acc[m][nt], afl[m], bh);
                    mma_bf16(acc[m][nt], afh[m], bl);
                }
            }
        }
    }

    // ---- epilogue ----
    const int g = lane >> 2, tig = lane & 3;
#pragma unroll
    for (int m = 0; m < 2; m++) {
#pragma unroll
        for (int nt = 0; nt < 8; nt++) {
            int col = wn + nt * 8 + 2 * tig;
            int r1 = row0 + wm + m * 16 + g;
            int r2 = r1 + 8;
            float b0 = 0.f, b1 = 0.f;
            if (mode > 0) { b0 = bias[col]; b1 = bias[col + 1]; }
            float v00 = acc[m][nt][0] + b0, v01 = acc[m][nt][1] + b1;
            float v10 = acc[m][nt][2] + b0, v11 = acc[m][nt][3] + b1;
            if (mode < 2) {
                if (r1 < NN) *(float2*)(outF + (size_t)r1 * 128 + col) = make_float2(v00, v01);
                if (r2 < NN) *(float2*)(outF + (size_t)r2 * 128 + col) = make_float2(v10, v11);
            } else {
                v00 = fmaxf(v00, 0.f); v01 = fmaxf(v01, 0.f);
                v10 = fmaxf(v10, 0.f); v11 = fmaxf(v11, 0.f);
                __nv_bfloat16 h0, l0, h1, l1;
                if (r1 < NN) {
                    split2(v00, h0, l0); split2(v01, h1, l1);
                    __nv_bfloat162 hh; hh.x = h0; hh.y = h1;
                    __nv_bfloat162 ll; ll.x = l0; ll.y = l1;
                    *(__nv_bfloat162*)(outH + (size_t)r1 * 128 + col) = hh;
                    *(__nv_bfloat162*)(outL + (size_t)r1 * 128 + col) = ll;
                }
                if (r2 < NN) {
                    split2(v10, h0, l0); split2(v11, h1, l1);
                    __nv_bfloat162 hh; hh.x = h0; hh.y = h1;
                    __nv_bfloat162 ll; ll.x = l0; ll.y = l1;
                    *(__nv_bfloat162*)(outH + (size_t)r2 * 128 + col) = hh;
                    *(__nv_bfloat162*)(outL + (size_t)r2 * 128 + col) = ll;
                }
            }
        }
    }
}

// ---------------------------------------------------------------------------
// conversions
// ---------------------------------------------------------------------------
__global__ void convert_obj_kernel(const float2* __restrict__ src,
                                   __nv_bfloat162* __restrict__ dh,
                                   __nv_bfloat162* __restrict__ dl, int n2)
{
    int i = blockIdx.x * blockDim.x + threadIdx.x;
    if (i >= n2) return;
    float2 v = src[i];
    __nv_bfloat16 h0, l0, h1, l1;
    split2(v.x, h0, l0);
    split2(v.y, h1, l1);
    __nv_bfloat162 hh; hh.x = h0; hh.y = h1;
    __nv_bfloat162 ll; ll.x = l0; ll.y = l1;
    dh[i] = hh; dl[i] = ll;
}

// transpose + split weights: src [L, K, N] -> dst [L, N, K]
__global__ void convert_wT_kernel(const float* __restrict__ src,
                                  __nv_bfloat16* __restrict__ dh,
                                  __nv_bfloat16* __restrict__ dl,
                                  int K, int N, int total)
{
    int i = blockIdx.x * blockDim.x + threadIdx.x;
    if (i >= total) return;
    int per = K * N;
    int l = i / per, r = i % per;
    int k = r / N, n = r % N;
    float v = src[i];
    __nv_bfloat16 h, lo;
    split2(v, h, lo);
    dh[(size_t)l * per + n * K + k] = h;
    dl[(size_t)l * per + n * K + k] = lo;
}

// ---------------------------------------------------------------------------
// Head GEMM (fp32, FFMA2): C[M,64] = A[M,128] @ B[128,64]
// ---------------------------------------------------------------------------
#define FMA2(acc, a, b) asm("fma.rn.f32x2 %0, %1, %2, %0;" : "+l"(acc) : "l"(a), "l"(b))
__device__ __forceinline__ unsigned long long dup_f32(float x) {
    unsigned long long r;
    asm("mov.b64 %0, {%1, %1};" : "=l"(r) : "f"(x));
    return r;
}
__device__ __forceinline__ void unpack2(unsigned long long v, float& lo, float& hi) {
    asm("mov.b64 {%0, %1}, %2;" : "=f"(lo), "=f"(hi) : "l"(v));
}

__global__ void __launch_bounds__(256)
gemm_head(const float* __restrict__ A, const float* __restrict__ B,
          float* __restrict__ C, int M)
{
    __shared__ float As[16][128 + 4];
    __shared__ float Bs[16][64];

    const int tid  = threadIdx.x;
    const int row0 = blockIdx.x * 128;
    const int trow = (tid / 16) * 8;
    const int tcol = (tid % 16) * 4;

    unsigned long long acc[8][2];
#pragma unroll
    for (int i = 0; i < 8; i++) acc[i][0] = acc[i][1] = 0ULL;

    for (int k0 = 0; k0 < 128; k0 += 16) {
#pragma unroll
        for (int v = 0; v < 2; v++) {
            int vid = tid + v * 256;
            int r = vid >> 2, k = (vid & 3) * 4;
            float4 t = make_float4(0.f, 0.f, 0.f, 0.f);
            int gr = row0 + r;
            if (gr < M) t = *(const float4*)&A[(size_t)gr * 128 + k0 + k];
            As[k + 0][r] = t.x; As[k + 1][r] = t.y; As[k + 2][r] = t.z; As[k + 3][r] = t.w;
        }
        {
            int bk = tid >> 4, c = (tid & 15) * 4;
            *(float4*)&Bs[bk][c] = *(const float4*)&B[(size_t)(k0 + bk) * 64 + c];
        }
        __syncthreads();
#pragma unroll
        for (int kk = 0; kk < 16; kk++) {
            float a[8];
            *(float4*)&a[0] = *(const float4*)&As[kk][trow];
            *(float4*)&a[4] = *(const float4*)&As[kk][trow + 4];
            float4 b = *(const float4*)&Bs[kk][tcol];
            unsigned long long b01 = ((const unsigned long long*)&b)[0];
            unsigned long long b23 = ((const unsigned long long*)&b)[1];
#pragma unroll
            for (int i = 0; i < 8; i++) {
                unsigned long long aa = dup_f32(a[i]);
                FMA2(acc[i][0], aa, b01);
                FMA2(acc[i][1], aa, b23);
            }
        }
        __syncthreads();
    }
#pragma unroll
    for (int i = 0; i < 8; i++) {
        int gr = row0 + trow + i;
        if (gr >= M) continue;
        float l0, h0, l1, h1;
        unpack2(acc[i][0], l0, h0);
        unpack2(acc[i][1], l1, h1);
        *(float4*)&C[(size_t)gr * 64 + tcol] = make_float4(l0, h0, l1, h1);
    }
}

// ---------------------------------------------------------------------------
// CSR construction
// ---------------------------------------------------------------------------
__global__ void zero_off_kernel(int* __restrict__ off)
{
    int i = blockIdx.x * blockDim.x + threadIdx.x;
    if (i <= NN) off[i] = 0;
}
__global__ void hist_kernel(const int* __restrict__ ei, int* __restrict__ off)
{
    int e = blockIdx.x * blockDim.x + threadIdx.x;
    if (e >= NE) return;
    atomicAdd(&off[ei[NE + e] + 1], 1);
}
__global__ void __launch_bounds__(1024)
scan_kernel(int* __restrict__ off, int* __restrict__ cur)
{
    __shared__ int part[1024];
    const int tid = threadIdx.x;
    const int chunk = (NN + 1023) / 1024;
    int start = 1 + tid * chunk;
    int end = start + chunk; if (end > NN + 1) end = NN + 1;
    int s = 0;
    for (int i = start; i < end; i++) s += off[i];
    part[tid] = s;
    __syncthreads();
    for (int d = 1; d < 1024; d <<= 1) {
        int v = (tid >= d) ? part[tid - d] : 0;
        __syncthreads();
        part[tid] += v;
        __syncthreads();
    }
    int run = (tid == 0) ? 0 : part[tid - 1];
    for (int i = start; i < end; i++) { run += off[i]; off[i] = run; }
    __syncthreads();
    for (int i = tid; i < NN; i += 1024) cur[i] = off[i];
}
__global__ void fill_kernel(const int* __restrict__ ei, int* __restrict__ cur,
                            int* __restrict__ csr)
{
    int e = blockIdx.x * blockDim.x + threadIdx.x;
    if (e >= NE) return;
    int p = atomicAdd(&cur[ei[NE + e]], 1);
    csr[p] = ei[e];
}

// ---------------------------------------------------------------------------
// Aggregates: x[n] = relu(z[n] + sum y[src])   (warp per node)
// ---------------------------------------------------------------------------
__global__ void aggregate_split_kernel(const float4* __restrict__ y4,
                                       const float4* __restrict__ z4,
                                       __nv_bfloat16* __restrict__ xh,
                                       __nv_bfloat16* __restrict__ xl,
                                       const int* __restrict__ off,
                                       const int* __restrict__ csr)
{
    int node = (blockIdx.x * blockDim.x + threadIdx.x) >> 5;
    int lane = threadIdx.x & 31;
    if (node >= NN) return;
    int s = off[node], e = off[node + 1];
    float4 acc = z4[(size_t)node * 32 + lane];
    for (int b = s; b < e; b += 32) {
        int idx = b + lane;
        int mysrc = (idx < e) ? csr[idx] : 0;
        int cnt = e - b; if (cnt > 32) cnt = 32;
        for (int j = 0; j < cnt; j++) {
            int src = __shfl_sync(0xffffffffu, mysrc, j);
            float4 v = y4[(size_t)src * 32 + lane];
            acc.x += v.x; acc.y += v.y; acc.z += v.z; acc.w += v.w;
        }
    }
    acc.x = fmaxf(acc.x, 0.f); acc.y = fmaxf(acc.y, 0.f);
    acc.z = fmaxf(acc.z, 0.f); acc.w = fmaxf(acc.w, 0.f);
    __nv_bfloat16 h0, l0, h1, l1, h2, l2, h3, l3;
    split2(acc.x, h0, l0); split2(acc.y, h1, l1);
    split2(acc.z, h2, l2); split2(acc.w, h3, l3);
    __nv_bfloat162 ha, hb, la, lb;
    ha.x = h0; ha.y = h1; hb.x = h2; hb.y = h3;
    la.x = l0; la.y = l1; lb.x = l2; lb.y = l3;
    size_t base = (size_t)node * 128 + lane * 4;
    *(__nv_bfloat162*)(xh + base)     = ha;
    *(__nv_bfloat162*)(xh + base + 2) = hb;
    *(__nv_bfloat162*)(xl + base)     = la;
    *(__nv_bfloat162*)(xl + base + 2) = lb;
}

__global__ void aggregate_f32_kernel(const float4* __restrict__ y4,
                                     const float4* __restrict__ z4,
                                     float4* __restrict__ x4,
                                     const int* __restrict__ off,
                                     const int* __restrict__ csr)
{
    int node = (blockIdx.x * blockDim.x + threadIdx.x) >> 5;
    int lane = threadIdx.x & 31;
    if (node >= NN) return;
    int s = off[node], e = off[node + 1];
    float4 acc = z4[(size_t)node * 32 + lane];
    for (int b = s; b < e; b += 32) {
        int idx = b + lane;
        int mysrc = (idx < e) ? csr[idx] : 0;
        int cnt = e - b; if (cnt > 32) cnt = 32;
        for (int j = 0; j < cnt; j++) {
            int src = __shfl_sync(0xffffffffu, mysrc, j);
            float4 v = y4[(size_t)src * 32 + lane];
            acc.x += v.x; acc.y += v.y; acc.z += v.z; acc.w += v.w;
        }
    }
    acc.x = fmaxf(acc.x, 0.f); acc.y = fmaxf(acc.y, 0.f);
    acc.z = fmaxf(acc.z, 0.f); acc.w = fmaxf(acc.w, 0.f);
    x4[(size_t)node * 32 + lane] = acc;
}

// ---------------------------------------------------------------------------
__global__ void pack_head_kernel(const float* __restrict__ hw,
                                 float* __restrict__ packed)
{
    int i = blockIdx.x * blockDim.x + threadIdx.x;
    if (i >= 128 * 64) return;
    int k = i / 64, c = i % 64;
    packed[i] = (c < 32) ? hw[k * CLS + c] : hw[(128 + k) * CLS + (c - 32)];
}

__global__ void edge_out_kernel(const float* __restrict__ fg,
                                const int* __restrict__ ei,
                                const float* __restrict__ head_b,
                                float* __restrict__ out)
{
    int warp = (blockIdx.x * blockDim.x + threadIdx.x) >> 5;
    int lane = threadIdx.x & 31;
    if (warp >= NE) return;
    int src = ei[warp];
    int dst = ei[NE + warp];
    float v = fg[(size_t)src * 64 + lane] + fg[(size_t)dst * 64 + 32 + lane] + head_b[lane];
    out[(size_t)warp * CLS + lane] = v;
}

// ---------------------------------------------------------------------------
extern "C" void kernel_launch(void* const* d_in, const int* in_sizes, int n_in,
                              void* d_out, int out_size)
{
    const float* obj    = (const float*)d_in[0];
    const int*   ei     = (const int*)d_in[1];   // int32 (JAX x64 disabled)
    const float* emb_w  = (const float*)d_in[2];
    const float* emb_b  = (const float*)d_in[3];
    const float* rel_w  = (const float*)d_in[4];
    const float* rel_b  = (const float*)d_in[5];
    const float* root_w = (const float*)d_in[6];
    const float* head_w = (const float*)d_in[7];
    const float* head_b = (const float*)d_in[8];
    float*       out    = (float*)d_out;

    float *x, *y, *z, *fg, *hw;
    int *off, *cur, *csr;
    __nv_bfloat16 *xh, *xl, *ohp, *olp, *ewh, *ewl, *rwh, *rwl, *owh, *owl;
    cudaGetSymbolAddress((void**)&x,   g_x);
    cudaGetSymbolAddress((void**)&y,   g_y);
    cudaGetSymbolAddress((void**)&z,   g_z);
    cudaGetSymbolAddress((void**)&fg,  g_fg);
    cudaGetSymbolAddress((void**)&hw,  g_hw);
    cudaGetSymbolAddress((void**)&off, g_off);
    cudaGetSymbolAddress((void**)&cur, g_cur);
    cudaGetSymbolAddress((void**)&csr, g_csr);
    cudaGetSymbolAddress((void**)&xh,  g_xh);
    cudaGetSymbolAddress((void**)&xl,  g_xl);
    cudaGetSymbolAddress((void**)&ohp, g_oh);
    cudaGetSymbolAddress((void**)&olp, g_ol);
    cudaGetSymbolAddress((void**)&ewh, g_ewh);
    cudaGetSymbolAddress((void**)&ewl, g_ewl);
    cudaGetSymbolAddress((void**)&rwh, g_rwh);
    cudaGetSymbolAddress((void**)&rwl, g_rwl);
    cudaGetSymbolAddress((void**)&owh, g_owh);
    cudaGetSymbolAddress((void**)&owl, g_owl);

    cudaFuncSetAttribute(gemm_mma, cudaFuncAttributeMaxDynamicSharedMemorySize, GSM_SIZE);

    const int gemm_gx   = (NN + 127) / 128;        // 391
    const int ne_blocks = (NE + 255) / 256;
    const int warp_blocks = (NE * 32 + 255) / 256;
    const int agg_blocks  = (NN * 32 + 255) / 256;

    // CSR build
    zero_off_kernel<<<(NN + 256) / 256, 256>>>(off);
    hist_kernel<<<ne_blocks, 256>>>(ei, off);
    scan_kernel<<<1, 1024>>>(off, cur);
    fill_kernel<<<ne_blocks, 256>>>(ei, cur, csr);

    // conversions
    convert_obj_kernel<<<(NN * FEAT / 2 + 255) / 256, 256>>>(
        (const float2*)obj, (__nv_bfloat162*)ohp, (__nv_bfloat162*)olp, NN * FEAT / 2);
    convert_wT_kernel<<<(256 * 128 + 255) / 256, 256>>>(emb_w, ewh, ewl, 256, 128, 256 * 128);
    convert_wT_kernel<<<(3 * 128 * 128 + 255) / 256, 256>>>(rel_w, rwh, rwl, 128, 128, 3 * 128 * 128);
    convert_wT_kernel<<<(3 * 128 * 128 + 255) / 256, 256>>>(root_w, owh, owl, 128, 128, 3 * 128 * 128);
    pack_head_kernel<<<(128 * 64 + 255) / 256, 256>>>(head_w, hw);

    // embedding: x(split bf16) = relu(obj @ emb_w + emb_b)
    gemm_mma<<<gemm_gx, 256, GSM_SIZE>>>(ohp, olp, ewh, ewl, emb_b,
                                         nullptr, xh, xl, 256, 2);

    // 3 GraphConv layers
    for (int l = 0; l < NLAYERS; l++) {
        gemm_mma<<<gemm_gx, 256, GSM_SIZE>>>(
            xh, xl, rwh + (size_t)l * 128 * 128, rwl + (size_t)l * 128 * 128,
            nullptr, y, nullptr, nullptr, 128, 0);
        gemm_mma<<<gemm_gx, 256, GSM_SIZE>>>(
            xh, xl, owh + (size_t)l * 128 * 128, owl + (size_t)l * 128 * 128,
            rel_b + (size_t)l * 128, z, nullptr, nullptr, 128, 1);
        if (l < NLAYERS - 1)
            aggregate_split_kernel<<<agg_blocks, 256>>>(
                (const float4*)y, (const float4*)z, xh, xl, off, csr);
        else
            aggregate_f32_kernel<<<agg_blocks, 256>>>(
                (const float4*)y, (const float4*)z, (float4*)x, off, csr);
    }

    // edge head
    gemm_head<<<gemm_gx, 256>>>(x, hw, fg, NN);
    edge_out_kernel<<<warp_blocks, 256>>>(fg, ei, head_b, out);
}

// round 10
// speedup vs baseline: 2.4499x; 1.0381x over previous
#include <cuda_runtime.h>
#include <cuda_bf16.h>
#include <cstdint>

constexpr int NN   = 50000;   // nodes
constexpr int NE   = 600000;  // edges
constexpr int FEAT = 256;
constexpr int HID  = 128;
constexpr int CLS  = 32;
constexpr int NLAYERS = 3;

// ---------------- device scratch (no allocs allowed) ----------------
__device__ float g_x [NN * HID];          // fp32 node features (final layer)
__device__ float g_y [NN * HID];          // y = x @ rel_w
__device__ float g_z [NN * HID];          // z = x @ root_w + b
__device__ float g_fg[NN * 64];
__device__ float g_hw[128 * 64];
__device__ int   g_off[NN + 1];
__device__ int   g_cur[NN];
__device__ int   g_csr[NE];

__device__ __nv_bfloat16 g_xh[NN * HID];   // split x (hi)
__device__ __nv_bfloat16 g_xl[NN * HID];   // split x (lo)
__device__ __nv_bfloat16 g_oh[NN * FEAT];  // split obj
__device__ __nv_bfloat16 g_ol[NN * FEAT];
__device__ __nv_bfloat16 g_ewh[128 * 256]; // emb_w^T hi  [N=128, K=256]
__device__ __nv_bfloat16 g_ewl[128 * 256];
__device__ __nv_bfloat16 g_rwh[3 * 128 * 128]; // rel_w^T
__device__ __nv_bfloat16 g_rwl[3 * 128 * 128];
__device__ __nv_bfloat16 g_owh[3 * 128 * 128]; // root_w^T
__device__ __nv_bfloat16 g_owl[3 * 128 * 128];

// ---------------- helpers ----------------
__device__ __forceinline__ uint32_t smem_u32(const void* p) {
    uint32_t a;
    asm("{ .reg .u64 t; cvta.to.shared.u64 t, %1; cvt.u32.u64 %0, t; }" : "=r"(a) : "l"(p));
    return a;
}
__device__ __forceinline__ void split2(float v, __nv_bfloat16& h, __nv_bfloat16& l) {
    h = __float2bfloat16_rn(v);
    l = __float2bfloat16_rn(v - __bfloat162float(h));
}
__device__ __forceinline__ void ldsm4(uint32_t* r, uint32_t addr) {
    asm volatile("ldmatrix.sync.aligned.m8n8.x4.shared.b16 {%0,%1,%2,%3}, [%4];"
        : "=r"(r[0]), "=r"(r[1]), "=r"(r[2]), "=r"(r[3]) : "r"(addr));
}
__device__ __forceinline__ void ldsm2(uint32_t* r, uint32_t addr) {
    asm volatile("ldmatrix.sync.aligned.m8n8.x2.shared.b16 {%0,%1}, [%2];"
        : "=r"(r[0]), "=r"(r[1]) : "r"(addr));
}
__device__ __forceinline__ void mma_bf16(float* c, const uint32_t* a, const uint32_t* b) {
    asm volatile(
        "mma.sync.aligned.m16n8k16.row.col.f32.bf16.bf16.f32 "
        "{%0,%1,%2,%3}, {%4,%5,%6,%7}, {%8,%9}, {%0,%1,%2,%3};"
        : "+f"(c[0]), "+f"(c[1]), "+f"(c[2]), "+f"(c[3])
        : "r"(a[0]), "r"(a[1]), "r"(a[2]), "r"(a[3]), "r"(b[0]), "r"(b[1]));
}

constexpr int KCH  = 128;
constexpr int KST  = KCH + 8;                 // padded smem stride (bf16)
constexpr int TILE_ELEMS = 128 * KST;         // 17408
constexpr int TILE_BYTES = TILE_ELEMS * 2;    // 34816
constexpr int GSM_SIZE   = 4 * TILE_BYTES;    // emb kernel: 4 tiles
constexpr int LSM_SIZE   = 6 * TILE_BYTES;    // fused layer kernel: 6 tiles (204KB)

// ---------------------------------------------------------------------------
// Fused layer GEMM (split-precision bf16 mma.sync):
//   Y = X @ rel_w           -> outY
//   Z = X @ root_w + bias   -> outZ
// X as splits (xh, xl); weights pre-transposed+split [N=128, K=128].
// K = 128 = one chunk: all 6 tiles staged once, no K loop.
// ---------------------------------------------------------------------------
__global__ void __launch_bounds__(256)
gemm_layer(const __nv_bfloat16* __restrict__ Ah, const __nv_bfloat16* __restrict__ Al,
           const __nv_bfloat16* __restrict__ Rh, const __nv_bfloat16* __restrict__ Rl,
           const __nv_bfloat16* __restrict__ Oh, const __nv_bfloat16* __restrict__ Ol,
           const float* __restrict__ bias,
           float* __restrict__ outY, float* __restrict__ outZ)
{
    extern __shared__ __nv_bfloat16 sm[];
    __nv_bfloat16* sAh = sm;
    __nv_bfloat16* sAl = sm + TILE_ELEMS;
    __nv_bfloat16* sRh = sm + 2 * TILE_ELEMS;
    __nv_bfloat16* sRl = sm + 3 * TILE_ELEMS;
    __nv_bfloat16* sOh = sm + 4 * TILE_ELEMS;
    __nv_bfloat16* sOl = sm + 5 * TILE_ELEMS;

    const int tid  = threadIdx.x;
    const int warp = tid >> 5, lane = tid & 31;
    const int row0 = blockIdx.x * 128;
    const int rows = NN - row0;
    const int wm = (warp >> 1) * 32;
    const int wn = (warp & 1) * 64;

    // ---- stage all tiles ----
#pragma unroll
    for (int v = 0; v < 8; v++) {
        int i = tid + v * 256;
        int r = i >> 4, c = (i & 15) * 8;
        uint4 t = make_uint4(0u, 0u, 0u, 0u);
        uint4 u = make_uint4(0u, 0u, 0u, 0u);
        if (r < rows) {
            t = *(const uint4*)(Ah + (size_t)(row0 + r) * 128 + c);
            u = *(const uint4*)(Al + (size_t)(row0 + r) * 128 + c);
        }
        *(uint4*)(sAh + r * KST + c) = t;
        *(uint4*)(sAl + r * KST + c) = u;
        *(uint4*)(sRh + r * KST + c) = *(const uint4*)(Rh + (size_t)r * 128 + c);
        *(uint4*)(sRl + r * KST + c) = *(const uint4*)(Rl + (size_t)r * 128 + c);
        *(uint4*)(sOh + r * KST + c) = *(const uint4*)(Oh + (size_t)r * 128 + c);
        *(uint4*)(sOl + r * KST + c) = *(const uint4*)(Ol + (size_t)r * 128 + c);
    }
    __syncthreads();

    float accY[2][8][4], accZ[2][8][4];
#pragma unroll
    for (int m = 0; m < 2; m++)
#pragma unroll
        for (int nt = 0; nt < 8; nt++)
#pragma unroll
            for (int j = 0; j < 4; j++) { accY[m][nt][j] = 0.f; accZ[m][nt][j] = 0.f; }

    const uint32_t uAh = smem_u32(sAh), uAl = smem_u32(sAl);
    const uint32_t uRh = smem_u32(sRh), uRl = smem_u32(sRl);
    const uint32_t uOh = smem_u32(sOh), uOl = smem_u32(sOl);

    const int rin  = lane & 7;
    const int quad = lane >> 3;
    const int a_radd = (quad & 1) * 8 + rin;
    const int a_cadd = (quad >> 1) * 16;
    const int b_l16  = lane & 15;
    const int b_radd = b_l16 & 7;
    const int b_cadd = (b_l16 >> 3) * 16;

#pragma unroll
    for (int ks = 0; ks < 8; ks++) {
        uint32_t afh[2][4], afl[2][4];
#pragma unroll
        for (int m = 0; m < 2; m++) {
            uint32_t off = (uint32_t)(wm + m * 16 + a_radd) * (KST * 2)
                         + (uint32_t)(ks * 32 + a_cadd);
            ldsm4(afh[m], uAh + off);
            ldsm4(afl[m], uAl + off);
        }
#pragma unroll
        for (int nt = 0; nt < 8; nt++) {
            uint32_t off = (uint32_t)(wn + nt * 8 + b_radd) * (KST * 2)
                         + (uint32_t)(ks * 32 + b_cadd);
            uint32_t rh[2], rl[2], oh[2], ol[2];
            ldsm2(rh, uRh + off);
            ldsm2(rl, uRl + off);
            ldsm2(oh, uOh + off);
            ldsm2(ol, uOl + off);
#pragma unroll
            for (int m = 0; m < 2; m++) {
                mma_bf16(accY[m][nt], afh[m], rh);
                mma_bf16(accY[m][nt], afl[m], rh);
                mma_bf16(accY[m][nt], afh[m], rl);
                mma_bf16(accZ[m][nt], afh[m], oh);
                mma_bf16(accZ[m][nt], afl[m], oh);
                mma_bf16(accZ[m][nt], afh[m], ol);
            }
        }
    }

    // ---- epilogue ----
    const int g = lane >> 2, tig = lane & 3;
#pragma unroll
    for (int m = 0; m < 2; m++) {
#pragma unroll
        for (int nt = 0; nt < 8; nt++) {
            int col = wn + nt * 8 + 2 * tig;
            int r1 = row0 + wm + m * 16 + g;
            int r2 = r1 + 8;
            float b0 = bias[col], b1 = bias[col + 1];
            if (r1 < NN) {
                *(float2*)(outY + (size_t)r1 * 128 + col) =
                    make_float2(accY[m][nt][0], accY[m][nt][1]);
                *(float2*)(outZ + (size_t)r1 * 128 + col) =
                    make_float2(accZ[m][nt][0] + b0, accZ[m][nt][1] + b1);
            }
            if (r2 < NN) {
                *(float2*)(outY + (size_t)r2 * 128 + col) =
                    make_float2(accY[m][nt][2], accY[m][nt][3]);
                *(float2*)(outZ + (size_t)r2 * 128 + col) =
                    make_float2(accZ[m][nt][2] + b0, accZ[m][nt][3] + b1);
            }
        }
    }
}

// ---------------------------------------------------------------------------
// Embedding GEMM (split bf16 mma.sync, K=256 in 2 chunks):
//   split(relu(obj @ emb_w + bias)) -> outH, outL
// ---------------------------------------------------------------------------
__global__ void __launch_bounds__(256)
gemm_emb(const __nv_bfloat16* __restrict__ Ah, const __nv_bfloat16* __restrict__ Al,
         const __nv_bfloat16* __restrict__ Bh, const __nv_bfloat16* __restrict__ Bl,
         const float* __restrict__ bias,
         __nv_bfloat16* __restrict__ outH, __nv_bfloat16* __restrict__ outL)
{
    extern __shared__ __nv_bfloat16 sm[];
    __nv_bfloat16* sAh = sm;
    __nv_bfloat16* sAl = sm + TILE_ELEMS;
    __nv_bfloat16* sBh = sm + 2 * TILE_ELEMS;
    __nv_bfloat16* sBl = sm + 3 * TILE_ELEMS;

    const int tid  = threadIdx.x;
    const int warp = tid >> 5, lane = tid & 31;
    const int row0 = blockIdx.x * 128;
    const int rows = NN - row0;
    const int wm = (warp >> 1) * 32;
    const int wn = (warp & 1) * 64;
    const int K = 256;

    float acc[2][8][4];
#pragma unroll
    for (int m = 0; m < 2; m++)
#pragma unroll
        for (int nt = 0; nt < 8; nt++)
#pragma unroll
            for (int j = 0; j < 4; j++) acc[m][nt][j] = 0.f;

    const uint32_t uAh = smem_u32(sAh), uAl = smem_u32(sAl);
    const uint32_t uBh = smem_u32(sBh), uBl = smem_u32(sBl);

    const int rin  = lane & 7;
    const int quad = lane >> 3;
    const int a_radd = (quad & 1) * 8 + rin;
    const int a_cadd = (quad >> 1) * 16;
    const int b_l16  = lane & 15;
    const int b_radd = b_l16 & 7;
    const int b_cadd = (b_l16 >> 3) * 16;

    for (int kc = 0; kc < K; kc += KCH) {
        if (kc) __syncthreads();
#pragma unroll
        for (int v = 0; v < 8; v++) {
            int i = tid + v * 256;
            int r = i >> 4, c = (i & 15) * 8;
            uint4 t = make_uint4(0u, 0u, 0u, 0u);
            uint4 u = make_uint4(0u, 0u, 0u, 0u);
            if (r < rows) {
                t = *(const uint4*)(Ah + (size_t)(row0 + r) * K + kc + c);
                u = *(const uint4*)(Al + (size_t)(row0 + r) * K + kc + c);
            }
            *(uint4*)(sAh + r * KST + c) = t;
            *(uint4*)(sAl + r * KST + c) = u;
            *(uint4*)(sBh + r * KST + c) = *(const uint4*)(Bh + (size_t)r * K + kc + c);
            *(uint4*)(sBl + r * KST + c) = *(const uint4*)(Bl + (size_t)r * K + kc + c);
        }
        __syncthreads();

#pragma unroll
        for (int ks = 0; ks < 8; ks++) {
            uint32_t afh[2][4], afl[2][4];
#pragma unroll
            for (int m = 0; m < 2; m++) {
                uint32_t off = (uint32_t)(wm + m * 16 + a_radd) * (KST * 2)
                             + (uint32_t)(ks * 32 + a_cadd);
                ldsm4(afh[m], uAh + off);
                ldsm4(afl[m], uAl + off);
            }
#pragma unroll
            for (int nt = 0; nt < 8; nt++) {
                uint32_t bh[2], bl[2];
                uint32_t off = (uint32_t)(wn + nt * 8 + b_radd) * (KST * 2)
                             + (uint32_t)(ks * 32 + b_cadd);
                ldsm2(bh, uBh + off);
                ldsm2(bl, uBl + off);
#pragma unroll
                for (int m = 0; m < 2; m++) {
                    mma_bf16(acc[m][nt], afh[m], bh);
                    mma_bf16(acc[m][nt], afl[m], bh);
                    mma_bf16(acc[m][nt], afh[m], bl);
                }
            }
        }
    }

    const int g = lane >> 2, tig = lane & 3;
#pragma unroll
    for (int m = 0; m < 2; m++) {
#pragma unroll
        for (int nt = 0; nt < 8; nt++) {
            int col = wn + nt * 8 + 2 * tig;
            int r1 = row0 + wm + m * 16 + g;
            int r2 = r1 + 8;
            float b0 = bias[col], b1 = bias[col + 1];
            float v00 = fmaxf(acc[m][nt][0] + b0, 0.f), v01 = fmaxf(acc[m][nt][1] + b1, 0.f);
            float v10 = fmaxf(acc[m][nt][2] + b0, 0.f), v11 = fmaxf(acc[m][nt][3] + b1, 0.f);
            __nv_bfloat16 h0, l0, h1, l1;
            if (r1 < NN) {
                split2(v00, h0, l0); split2(v01, h1, l1);
                __nv_bfloat162 hh; hh.x = h0; hh.y = h1;
                __nv_bfloat162 ll; ll.x = l0; ll.y = l1;
                *(__nv_bfloat162*)(outH + (size_t)r1 * 128 + col) = hh;
                *(__nv_bfloat162*)(outL + (size_t)r1 * 128 + col) = ll;
            }
            if (r2 < NN) {
                split2(v10, h0, l0); split2(v11, h1, l1);
                __nv_bfloat162 hh; hh.x = h0; hh.y = h1;
                __nv_bfloat162 ll; ll.x = l0; ll.y = l1;
                *(__nv_bfloat162*)(outH + (size_t)r2 * 128 + col) = hh;
                *(__nv_bfloat162*)(outL + (size_t)r2 * 128 + col) = ll;
            }
        }
    }
}

// ---------------------------------------------------------------------------
// conversions
// ---------------------------------------------------------------------------
__global__ void convert_obj_kernel(const float2* __restrict__ src,
                                   __nv_bfloat162* __restrict__ dh,
                                   __nv_bfloat162* __restrict__ dl, int n2)
{
    int i = blockIdx.x * blockDim.x + threadIdx.x;
    if (i >= n2) return;
    float2 v = src[i];
    __nv_bfloat16 h0, l0, h1, l1;
    split2(v.x, h0, l0);
    split2(v.y, h1, l1);
    __nv_bfloat162 hh; hh.x = h0; hh.y = h1;
    __nv_bfloat162 ll; ll.x = l0; ll.y = l1;
    dh[i] = hh; dl[i] = ll;
}

// transpose + split weights: src [L, K, N] -> dst [L, N, K]
__global__ void convert_wT_kernel(const float* __restrict__ src,
                                  __nv_bfloat16* __restrict__ dh,
                                  __nv_bfloat16* __restrict__ dl,
                                  int K, int N, int total)
{
    int i = blockIdx.x * blockDim.x + threadIdx.x;
    if (i >= total) return;
    int per = K * N;
    int l = i / per, r = i % per;
    int k = r / N, n = r % N;
    float v = src[i];
    __nv_bfloat16 h, lo;
    split2(v, h, lo);
    dh[(size_t)l * per + n * K + k] = h;
    dl[(size_t)l * per + n * K + k] = lo;
}

// ---------------------------------------------------------------------------
// Head GEMM (fp32, FFMA2): C[M,64] = A[M,128] @ B[128,64]
// ---------------------------------------------------------------------------
#define FMA2(acc, a, b) asm("fma.rn.f32x2 %0, %1, %2, %0;" : "+l"(acc) : "l"(a), "l"(b))
__device__ __forceinline__ unsigned long long dup_f32(float x) {
    unsigned long long r;
    asm("mov.b64 %0, {%1, %1};" : "=l"(r) : "f"(x));
    return r;
}
__device__ __forceinline__ void unpack2(unsigned long long v, float& lo, float& hi) {
    asm("mov.b64 {%0, %1}, %2;" : "=f"(lo), "=f"(hi) : "l"(v));
}

__global__ void __launch_bounds__(256)
gemm_head(const float* __restrict__ A, const float* __restrict__ B,
          float* __restrict__ C, int M)
{
    __shared__ float As[16][128 + 4];
    __shared__ float Bs[16][64];

    const int tid  = threadIdx.x;
    const int row0 = blockIdx.x * 128;
    const int trow = (tid / 16) * 8;
    const int tcol = (tid % 16) * 4;

    unsigned long long acc[8][2];
#pragma unroll
    for (int i = 0; i < 8; i++) acc[i][0] = acc[i][1] = 0ULL;

    for (int k0 = 0; k0 < 128; k0 += 16) {
#pragma unroll
        for (int v = 0; v < 2; v++) {
            int vid = tid + v * 256;
            int r = vid >> 2, k = (vid & 3) * 4;
            float4 t = make_float4(0.f, 0.f, 0.f, 0.f);
            int gr = row0 + r;
            if (gr < M) t = *(const float4*)&A[(size_t)gr * 128 + k0 + k];
            As[k + 0][r] = t.x; As[k + 1][r] = t.y; As[k + 2][r] = t.z; As[k + 3][r] = t.w;
        }
        {
            int bk = tid >> 4, c = (tid & 15) * 4;
            *(float4*)&Bs[bk][c] = *(const float4*)&B[(size_t)(k0 + bk) * 64 + c];
        }
        __syncthreads();
#pragma unroll
        for (int kk = 0; kk < 16; kk++) {
            float a[8];
            *(float4*)&a[0] = *(const float4*)&As[kk][trow];
            *(float4*)&a[4] = *(const float4*)&As[kk][trow + 4];
            float4 b = *(const float4*)&Bs[kk][tcol];
            unsigned long long b01 = ((const unsigned long long*)&b)[0];
            unsigned long long b23 = ((const unsigned long long*)&b)[1];
#pragma unroll
            for (int i = 0; i < 8; i++) {
                unsigned long long aa = dup_f32(a[i]);
                FMA2(acc[i][0], aa, b01);
                FMA2(acc[i][1], aa, b23);
            }
        }
        __syncthreads();
    }
#pragma unroll
    for (int i = 0; i < 8; i++) {
        int gr = row0 + trow + i;
        if (gr >= M) continue;
        float l0, h0, l1, h1;
        unpack2(acc[i][0], l0, h0);
        unpack2(acc[i][1], l1, h1);
        *(float4*)&C[(size_t)gr * 64 + tcol] = make_float4(l0, h0, l1, h1);
    }
}

// ---------------------------------------------------------------------------
// CSR construction
// ---------------------------------------------------------------------------
__global__ void zero_off_kernel(int* __restrict__ off)
{
    int i = blockIdx.x * blockDim.x + threadIdx.x;
    if (i <= NN) off[i] = 0;
}
__global__ void hist_kernel(const int* __restrict__ ei, int* __restrict__ off)
{
    int e = blockIdx.x * blockDim.x + threadIdx.x;
    if (e >= NE) return;
    atomicAdd(&off[ei[NE + e] + 1], 1);
}
__global__ void __launch_bounds__(1024)
scan_kernel(int* __restrict__ off, int* __restrict__ cur)
{
    __shared__ int part[1024];
    const int tid = threadIdx.x;
    const int chunk = (NN + 1023) / 1024;
    int start = 1 + tid * chunk;
    int end = start + chunk; if (end > NN + 1) end = NN + 1;
    int s = 0;
    for (int i = start; i < end; i++) s += off[i];
    part[tid] = s;
    __syncthreads();
    for (int d = 1; d < 1024; d <<= 1) {
        int v = (tid >= d) ? part[tid - d] : 0;
        __syncthreads();
        part[tid] += v;
        __syncthreads();
    }
    int run = (tid == 0) ? 0 : part[tid - 1];
    for (int i = start; i < end; i++) { run += off[i]; off[i] = run; }
    __syncthreads();
    for (int i = tid; i < NN; i += 1024) cur[i] = off[i];
}
__global__ void fill_kernel(const int* __restrict__ ei, int* __restrict__ cur,
                            int* __restrict__ csr)
{
    int e = blockIdx.x * blockDim.x + threadIdx.x;
    if (e >= NE) return;
    int p = atomicAdd(&cur[ei[NE + e]], 1);
    csr[p] = ei[e];
}

// ---------------------------------------------------------------------------
// Aggregates: x[n] = relu(z[n] + sum y[src])   (warp per node)
// ---------------------------------------------------------------------------
__global__ void aggregate_split_kernel(const float4* __restrict__ y4,
                                       const float4* __restrict__ z4,
                                       __nv_bfloat16* __restrict__ xh,
                                       __nv_bfloat16* __restrict__ xl,
                                       const int* __restrict__ off,
                                       const int* __restrict__ csr)
{
    int node = (blockIdx.x * blockDim.x + threadIdx.x) >> 5;
    int lane = threadIdx.x & 31;
    if (node >= NN) return;
    int s = off[node], e = off[node + 1];
    float4 acc = z4[(size_t)node * 32 + lane];
    for (int b = s; b < e; b += 32) {
        int idx = b + lane;
        int mysrc = (idx < e) ? csr[idx] : 0;
        int cnt = e - b; if (cnt > 32) cnt = 32;
        for (int j = 0; j < cnt; j++) {
            int src = __shfl_sync(0xffffffffu, mysrc, j);
            float4 v = y4[(size_t)src * 32 + lane];
            acc.x += v.x; acc.y += v.y; acc.z += v.z; acc.w += v.w;
        }
    }
    acc.x = fmaxf(acc.x, 0.f); acc.y = fmaxf(acc.y, 0.f);
    acc.z = fmaxf(acc.z, 0.f); acc.w = fmaxf(acc.w, 0.f);
    __nv_bfloat16 h0, l0, h1, l1, h2, l2, h3, l3;
    split2(acc.x, h0, l0); split2(acc.y, h1, l1);
    split2(acc.z, h2, l2); split2(acc.w, h3, l3);
    __nv_bfloat162 ha, hb, la, lb;
    ha.x = h0; ha.y = h1; hb.x = h2; hb.y = h3;
    la.x = l0; la.y = l1; lb.x = l2; lb.y = l3;
    size_t base = (size_t)node * 128 + lane * 4;
    *(__nv_bfloat162*)(xh + base)     = ha;
    *(__nv_bfloat162*)(xh + base + 2) = hb;
    *(__nv_bfloat162*)(xl + base)     = la;
    *(__nv_bfloat162*)(xl + base + 2) = lb;
}

__global__ void aggregate_f32_kernel(const float4* __restrict__ y4,
                                     const float4* __restrict__ z4,
                                     float4* __restrict__ x4,
                                     const int* __restrict__ off,
                                     const int* __restrict__ csr)
{
    int node = (blockIdx.x * blockDim.x + threadIdx.x) >> 5;
    int lane = threadIdx.x & 31;
    if (node >= NN) return;
    int s = off[node], e = off[node + 1];
    float4 acc = z4[(size_t)node * 32 + lane];
    for (int b = s; b < e; b += 32) {
        int idx = b + lane;
        int mysrc = (idx < e) ? csr[idx] : 0;
        int cnt = e - b; if (cnt > 32) cnt = 32;
        for (int j = 0; j < cnt; j++) {
            int src = __shfl_sync(0xffffffffu, mysrc, j);
            float4 v = y4[(size_t)src * 32 + lane];
            acc.x += v.x; acc.y += v.y; acc.z += v.z; acc.w += v.w;
        }
    }
    acc.x = fmaxf(acc.x, 0.f); acc.y = fmaxf(acc.y, 0.f);
    acc.z = fmaxf(acc.z, 0.f); acc.w = fmaxf(acc.w, 0.f);
    x4[(size_t)node * 32 + lane] = acc;
}

// ---------------------------------------------------------------------------
__global__ void pack_head_kernel(const float* __restrict__ hw,
                                 float* __restrict__ packed)
{
    int i = blockIdx.x * blockDim.x + threadIdx.x;
    if (i >= 128 * 64) return;
    int k = i / 64, c = i % 64;
    packed[i] = (c < 32) ? hw[k * CLS + c] : hw[(128 + k) * CLS + (c - 32)];
}

__global__ void edge_out_kernel(const float* __restrict__ fg,
                                const int* __restrict__ ei,
                                const float* __restrict__ head_b,
                                float* __restrict__ out)
{
    int warp = (blockIdx.x * blockDim.x + threadIdx.x) >> 5;
    int lane = threadIdx.x & 31;
    if (warp >= NE) return;
    int src = ei[warp];
    int dst = ei[NE + warp];
    float v = fg[(size_t)src * 64 + lane] + fg[(size_t)dst * 64 + 32 + lane] + head_b[lane];
    out[(size_t)warp * CLS + lane] = v;
}

// ---------------------------------------------------------------------------
extern "C" void kernel_launch(void* const* d_in, const int* in_sizes, int n_in,
                              void* d_out, int out_size)
{
    const float* obj    = (const float*)d_in[0];
    const int*   ei     = (const int*)d_in[1];   // int32 (JAX x64 disabled)
    const float* emb_w  = (const float*)d_in[2];
    const float* emb_b  = (const float*)d_in[3];
    const float* rel_w  = (const float*)d_in[4];
    const float* rel_b  = (const float*)d_in[5];
    const float* root_w = (const float*)d_in[6];
    const float* head_w = (const float*)d_in[7];
    const float* head_b = (const float*)d_in[8];
    float*       out    = (float*)d_out;

    float *x, *y, *z, *fg, *hw;
    int *off, *cur, *csr;
    __nv_bfloat16 *xh, *xl, *ohp, *olp, *ewh, *ewl, *rwh, *rwl, *owh, *owl;
    cudaGetSymbolAddress((void**)&x,   g_x);
    cudaGetSymbolAddress((void**)&y,   g_y);
    cudaGetSymbolAddress((void**)&z,   g_z);
    cudaGetSymbolAddress((void**)&fg,  g_fg);
    cudaGetSymbolAddress((void**)&hw,  g_hw);
    cudaGetSymbolAddress((void**)&off, g_off);
    cudaGetSymbolAddress((void**)&cur, g_cur);
    cudaGetSymbolAddress((void**)&csr, g_csr);
    cudaGetSymbolAddress((void**)&xh,  g_xh);
    cudaGetSymbolAddress((void**)&xl,  g_xl);
    cudaGetSymbolAddress((void**)&ohp, g_oh);
    cudaGetSymbolAddress((void**)&olp, g_ol);
    cudaGetSymbolAddress((void**)&ewh, g_ewh);
    cudaGetSymbolAddress((void**)&ewl, g_ewl);
    cudaGetSymbolAddress((void**)&rwh, g_rwh);
    cudaGetSymbolAddress((void**)&rwl, g_rwl);
    cudaGetSymbolAddress((void**)&owh, g_owh);
    cudaGetSymbolAddress((void**)&owl, g_owl);

    cudaFuncSetAttribute(gemm_emb,   cudaFuncAttributeMaxDynamicSharedMemorySize, GSM_SIZE);
    cudaFuncSetAttribute(gemm_layer, cudaFuncAttributeMaxDynamicSharedMemorySize, LSM_SIZE);

    const int gemm_gx   = (NN + 127) / 128;        // 391
    const int ne_blocks = (NE + 255) / 256;
    const int warp_blocks = (NE * 32 + 255) / 256;
    const int agg_blocks  = (NN * 32 + 255) / 256;

    // CSR build
    zero_off_kernel<<<(NN + 256) / 256, 256>>>(off);
    hist_kernel<<<ne_blocks, 256>>>(ei, off);
    scan_kernel<<<1, 1024>>>(off, cur);
    fill_kernel<<<ne_blocks, 256>>>(ei, cur, csr);

    // conversions
    convert_obj_kernel<<<(NN * FEAT / 2 + 255) / 256, 256>>>(
        (const float2*)obj, (__nv_bfloat162*)ohp, (__nv_bfloat162*)olp, NN * FEAT / 2);
    convert_wT_kernel<<<(256 * 128 + 255) / 256, 256>>>(emb_w, ewh, ewl, 256, 128, 256 * 128);
    convert_wT_kernel<<<(3 * 128 * 128 + 255) / 256, 256>>>(rel_w, rwh, rwl, 128, 128, 3 * 128 * 128);
    convert_wT_kernel<<<(3 * 128 * 128 + 255) / 256, 256>>>(root_w, owh, owl, 128, 128, 3 * 128 * 128);
    pack_head_kernel<<<(128 * 64 + 255) / 256, 256>>>(head_w, hw);

    // embedding: x(split bf16) = relu(obj @ emb_w + emb_b)
    gemm_emb<<<gemm_gx, 256, GSM_SIZE>>>(ohp, olp, ewh, ewl, emb_b, xh, xl);

    // 3 GraphConv layers (fused Y/Z GEMM per layer)
    for (int l = 0; l < NLAYERS; l++) {
        gemm_layer<<<gemm_gx, 256, LSM_SIZE>>>(
            xh, xl,
            rwh + (size_t)l * 128 * 128, rwl + (size_t)l * 128 * 128,
            owh + (size_t)l * 128 * 128, owl + (size_t)l * 128 * 128,
            rel_b + (size_t)l * 128, y, z);
        if (l < NLAYERS - 1)
            aggregate_split_kernel<<<agg_blocks, 256>>>(
                (const float4*)y, (const float4*)z, xh, xl, off, csr);
        else
            aggregate_f32_kernel<<<agg_blocks, 256>>>(
                (const float4*)y, (const float4*)z, (float4*)x, off, csr);
    }

    // edge head
    gemm_head<<<gemm_gx, 256>>>(x, hw, fg, NN);
    edge_out_kernel<<<warp_blocks, 256>>>(fg, ei, head_b, out);
}

// round 12
// speedup vs baseline: 2.5606x; 1.0452x over previous
#include <cuda_runtime.h>
#include <cuda_bf16.h>
#include <cstdint>

constexpr int NN   = 50000;   // nodes
constexpr int NE   = 600000;  // edges
constexpr int FEAT = 256;
constexpr int HID  = 128;
constexpr int CLS  = 32;
constexpr int NLAYERS = 3;

// ---------------- device scratch (no allocs allowed) ----------------
__device__ float g_x [NN * HID];          // fp32 node features (final layer)
__device__ float g_y [NN * HID];          // y = x @ rel_w
__device__ float g_z [NN * HID];          // z = x @ root_w + b
__device__ float g_fg[NN * 64];
__device__ float g_hw[128 * 64];
__device__ int   g_off[NN + 1];
__device__ int   g_cur[NN];
__device__ int   g_csr[NE];

__device__ __nv_bfloat16 g_xh[NN * HID];   // split x (hi)
__device__ __nv_bfloat16 g_xl[NN * HID];   // split x (lo)
__device__ __nv_bfloat16 g_ewh[128 * 256]; // emb_w^T hi  [N=128, K=256]
__device__ __nv_bfloat16 g_ewl[128 * 256];
__device__ __nv_bfloat16 g_rwh[3 * 128 * 128]; // rel_w^T
__device__ __nv_bfloat16 g_rwl[3 * 128 * 128];
__device__ __nv_bfloat16 g_owh[3 * 128 * 128]; // root_w^T
__device__ __nv_bfloat16 g_owl[3 * 128 * 128];

// ---------------- helpers ----------------
__device__ __forceinline__ uint32_t smem_u32(const void* p) {
    uint32_t a;
    asm("{ .reg .u64 t; cvta.to.shared.u64 t, %1; cvt.u32.u64 %0, t; }" : "=r"(a) : "l"(p));
    return a;
}
__device__ __forceinline__ void split2(float v, __nv_bfloat16& h, __nv_bfloat16& l) {
    h = __float2bfloat16_rn(v);
    l = __float2bfloat16_rn(v - __bfloat162float(h));
}
__device__ __forceinline__ void ldsm4(uint32_t* r, uint32_t addr) {
    asm volatile("ldmatrix.sync.aligned.m8n8.x4.shared.b16 {%0,%1,%2,%3}, [%4];"
        : "=r"(r[0]), "=r"(r[1]), "=r"(r[2]), "=r"(r[3]) : "r"(addr));
}
__device__ __forceinline__ void ldsm2(uint32_t* r, uint32_t addr) {
    asm volatile("ldmatrix.sync.aligned.m8n8.x2.shared.b16 {%0,%1}, [%2];"
        : "=r"(r[0]), "=r"(r[1]) : "r"(addr));
}
__device__ __forceinline__ void mma_bf16(float* c, const uint32_t* a, const uint32_t* b) {
    asm volatile(
        "mma.sync.aligned.m16n8k16.row.col.f32.bf16.bf16.f32 "
        "{%0,%1,%2,%3}, {%4,%5,%6,%7}, {%8,%9}, {%0,%1,%2,%3};"
        : "+f"(c[0]), "+f"(c[1]), "+f"(c[2]), "+f"(c[3])
        : "r"(a[0]), "r"(a[1]), "r"(a[2]), "r"(a[3]), "r"(b[0]), "r"(b[1]));
}

constexpr int KCH  = 128;
constexpr int KST  = KCH + 8;                 // padded smem stride (bf16)
constexpr int TILE_ELEMS = 128 * KST;         // 17408
constexpr int TILE_BYTES = TILE_ELEMS * 2;    // 34816
constexpr int GSM_SIZE   = 4 * TILE_BYTES;    // emb kernel: 4 tiles
constexpr int LSM_SIZE   = 6 * TILE_BYTES;    // fused layer kernel: 6 tiles (204KB)

// ---------------------------------------------------------------------------
// Fused layer GEMM (split-precision bf16 mma.sync):
//   Y = X @ rel_w           -> outY
//   Z = X @ root_w + bias   -> outZ
// ---------------------------------------------------------------------------
__global__ void __launch_bounds__(256)
gemm_layer(const __nv_bfloat16* __restrict__ Ah, const __nv_bfloat16* __restrict__ Al,
           const __nv_bfloat16* __restrict__ Rh, const __nv_bfloat16* __restrict__ Rl,
           const __nv_bfloat16* __restrict__ Oh, const __nv_bfloat16* __restrict__ Ol,
           const float* __restrict__ bias,
           float* __restrict__ outY, float* __restrict__ outZ)
{
    extern __shared__ __nv_bfloat16 sm[];
    __nv_bfloat16* sAh = sm;
    __nv_bfloat16* sAl = sm + TILE_ELEMS;
    __nv_bfloat16* sRh = sm + 2 * TILE_ELEMS;
    __nv_bfloat16* sRl = sm + 3 * TILE_ELEMS;
    __nv_bfloat16* sOh = sm + 4 * TILE_ELEMS;
    __nv_bfloat16* sOl = sm + 5 * TILE_ELEMS;

    const int tid  = threadIdx.x;
    const int warp = tid >> 5, lane = tid & 31;
    const int row0 = blockIdx.x * 128;
    const int rows = NN - row0;
    const int wm = (warp >> 1) * 32;
    const int wn = (warp & 1) * 64;

#pragma unroll
    for (int v = 0; v < 8; v++) {
        int i = tid + v * 256;
        int r = i >> 4, c = (i & 15) * 8;
        uint4 t = make_uint4(0u, 0u, 0u, 0u);
        uint4 u = make_uint4(0u, 0u, 0u, 0u);
        if (r < rows) {
            t = *(const uint4*)(Ah + (size_t)(row0 + r) * 128 + c);
            u = *(const uint4*)(Al + (size_t)(row0 + r) * 128 + c);
        }
        *(uint4*)(sAh + r * KST + c) = t;
        *(uint4*)(sAl + r * KST + c) = u;
        *(uint4*)(sRh + r * KST + c) = *(const uint4*)(Rh + (size_t)r * 128 + c);
        *(uint4*)(sRl + r * KST + c) = *(const uint4*)(Rl + (size_t)r * 128 + c);
        *(uint4*)(sOh + r * KST + c) = *(const uint4*)(Oh + (size_t)r * 128 + c);
        *(uint4*)(sOl + r * KST + c) = *(const uint4*)(Ol + (size_t)r * 128 + c);
    }
    __syncthreads();

    float accY[2][8][4], accZ[2][8][4];
#pragma unroll
    for (int m = 0; m < 2; m++)
#pragma unroll
        for (int nt = 0; nt < 8; nt++)
#pragma unroll
            for (int j = 0; j < 4; j++) { accY[m][nt][j] = 0.f; accZ[m][nt][j] = 0.f; }

    const uint32_t uAh = smem_u32(sAh), uAl = smem_u32(sAl);
    const uint32_t uRh = smem_u32(sRh), uRl = smem_u32(sRl);
    const uint32_t uOh = smem_u32(sOh), uOl = smem_u32(sOl);

    const int rin  = lane & 7;
    const int quad = lane >> 3;
    const int a_radd = (quad & 1) * 8 + rin;
    const int a_cadd = (quad >> 1) * 16;
    const int b_l16  = lane & 15;
    const int b_radd = b_l16 & 7;
    const int b_cadd = (b_l16 >> 3) * 16;

#pragma unroll
    for (int ks = 0; ks < 8; ks++) {
        uint32_t afh[2][4], afl[2][4];
#pragma unroll
        for (int m = 0; m < 2; m++) {
            uint32_t off = (uint32_t)(wm + m * 16 + a_radd) * (KST * 2)
                         + (uint32_t)(ks * 32 + a_cadd);
            ldsm4(afh[m], uAh + off);
            ldsm4(afl[m], uAl + off);
        }
#pragma unroll
        for (int nt = 0; nt < 8; nt++) {
            uint32_t off = (uint32_t)(wn + nt * 8 + b_radd) * (KST * 2)
                         + (uint32_t)(ks * 32 + b_cadd);
            uint32_t rh[2], rl[2], oh[2], ol[2];
            ldsm2(rh, uRh + off);
            ldsm2(rl, uRl + off);
            ldsm2(oh, uOh + off);
            ldsm2(ol, uOl + off);
#pragma unroll
            for (int m = 0; m < 2; m++) {
                mma_bf16(accY[m][nt], afh[m], rh);
                mma_bf16(accY[m][nt], afl[m], rh);
                mma_bf16(accY[m][nt], afh[m], rl);
                mma_bf16(accZ[m][nt], afh[m], oh);
                mma_bf16(accZ[m][nt], afl[m], oh);
                mma_bf16(accZ[m][nt], afh[m], ol);
            }
        }
    }

    const int g = lane >> 2, tig = lane & 3;
#pragma unroll
    for (int m = 0; m < 2; m++) {
#pragma unroll
        for (int nt = 0; nt < 8; nt++) {
            int col = wn + nt * 8 + 2 * tig;
            int r1 = row0 + wm + m * 16 + g;
            int r2 = r1 + 8;
            float b0 = bias[col], b1 = bias[col + 1];
            if (r1 < NN) {
                *(float2*)(outY + (size_t)r1 * 128 + col) =
                    make_float2(accY[m][nt][0], accY[m][nt][1]);
                *(float2*)(outZ + (size_t)r1 * 128 + col) =
                    make_float2(accZ[m][nt][0] + b0, accZ[m][nt][1] + b1);
            }
            if (r2 < NN) {
                *(float2*)(outY + (size_t)r2 * 128 + col) =
                    make_float2(accY[m][nt][2], accY[m][nt][3]);
                *(float2*)(outZ + (size_t)r2 * 128 + col) =
                    make_float2(accZ[m][nt][2] + b0, accZ[m][nt][3] + b1);
            }
        }
    }
}

// ---------------------------------------------------------------------------
// Embedding GEMM (split bf16 mma.sync, K=256 in 2 chunks):
//   split(relu(obj @ emb_w + bias)) -> outH, outL
// A is fp32 obj; split done in staging (no separate conversion pass).
// ---------------------------------------------------------------------------
__global__ void __launch_bounds__(256)
gemm_emb(const float* __restrict__ A,
         const __nv_bfloat16* __restrict__ Bh, const __nv_bfloat16* __restrict__ Bl,
         const float* __restrict__ bias,
         __nv_bfloat16* __restrict__ outH, __nv_bfloat16* __restrict__ outL)
{
    extern __shared__ __nv_bfloat16 sm[];
    __nv_bfloat16* sAh = sm;
    __nv_bfloat16* sAl = sm + TILE_ELEMS;
    __nv_bfloat16* sBh = sm + 2 * TILE_ELEMS;
    __nv_bfloat16* sBl = sm + 3 * TILE_ELEMS;

    const int tid  = threadIdx.x;
    const int warp = tid >> 5, lane = tid & 31;
    const int row0 = blockIdx.x * 128;
    const int rows = NN - row0;
    const int wm = (warp >> 1) * 32;
    const int wn = (warp & 1) * 64;
    const int K = 256;

    float acc[2][8][4];
#pragma unroll
    for (int m = 0; m < 2; m++)
#pragma unroll
        for (int nt = 0; nt < 8; nt++)
#pragma unroll
            for (int j = 0; j < 4; j++) acc[m][nt][j] = 0.f;

    const uint32_t uAh = smem_u32(sAh), uAl = smem_u32(sAl);
    const uint32_t uBh = smem_u32(sBh), uBl = smem_u32(sBl);

    const int rin  = lane & 7;
    const int quad = lane >> 3;
    const int a_radd = (quad & 1) * 8 + rin;
    const int a_cadd = (quad >> 1) * 16;
    const int b_l16  = lane & 15;
    const int b_radd = b_l16 & 7;
    const int b_cadd = (b_l16 >> 3) * 16;

    for (int kc = 0; kc < K; kc += KCH) {
        if (kc) __syncthreads();
        // A: fp32 load + in-register split (128 rows x 128 cols per chunk)
#pragma unroll
        for (int v = 0; v < 16; v++) {
            int i = tid + v * 256;
            int r = i >> 5, c4 = (i & 31) * 4;
            float4 t = make_float4(0.f, 0.f, 0.f, 0.f);
            if (r < rows)
                t = *(const float4*)(A + (size_t)(row0 + r) * K + kc + c4);
            __nv_bfloat16 h0, l0, h1, l1, h2, l2, h3, l3;
            split2(t.x, h0, l0); split2(t.y, h1, l1);
            split2(t.z, h2, l2); split2(t.w, h3, l3);
            __nv_bfloat162 ha, hb, la, lb;
            ha.x = h0; ha.y = h1; hb.x = h2; hb.y = h3;
            la.x = l0; la.y = l1; lb.x = l2; lb.y = l3;
            *(__nv_bfloat162*)(sAh + r * KST + c4)     = ha;
            *(__nv_bfloat162*)(sAh + r * KST + c4 + 2) = hb;
            *(__nv_bfloat162*)(sAl + r * KST + c4)     = la;
            *(__nv_bfloat162*)(sAl + r * KST + c4 + 2) = lb;
        }
        // B: bf16 tiles
#pragma unroll
        for (int v = 0; v < 8; v++) {
            int i = tid + v * 256;
            int r = i >> 4, c = (i & 15) * 8;
            *(uint4*)(sBh + r * KST + c) = *(const uint4*)(Bh + (size_t)r * K + kc + c);
            *(uint4*)(sBl + r * KST + c) = *(const uint4*)(Bl + (size_t)r * K + kc + c);
        }
        __syncthreads();

#pragma unroll
        for (int ks = 0; ks < 8; ks++) {
            uint32_t afh[2][4], afl[2][4];
#pragma unroll
            for (int m = 0; m < 2; m++) {
                uint32_t off = (uint32_t)(wm + m * 16 + a_radd) * (KST * 2)
                             + (uint32_t)(ks * 32 + a_cadd);
                ldsm4(afh[m], uAh + off);
                ldsm4(afl[m], uAl + off);
            }
#pragma unroll
            for (int nt = 0; nt < 8; nt++) {
                uint32_t bh[2], bl[2];
                uint32_t off = (uint32_t)(wn + nt * 8 + b_radd) * (KST * 2)
                             + (uint32_t)(ks * 32 + b_cadd);
                ldsm2(bh, uBh + off);
                ldsm2(bl, uBl + off);
#pragma unroll
                for (int m = 0; m < 2; m++) {
                    mma_bf16(acc[m][nt], afh[m], bh);
                    mma_bf16(acc[m][nt], afl[m], bh);
                    mma_bf16(acc[m][nt], afh[m], bl);
                }
            }
        }
    }

    const int g = lane >> 2, tig = lane & 3;
#pragma unroll
    for (int m = 0; m < 2; m++) {
#pragma unroll
        for (int nt = 0; nt < 8; nt++) {
            int col = wn + nt * 8 + 2 * tig;
            int r1 = row0 + wm + m * 16 + g;
            int r2 = r1 + 8;
            float b0 = bias[col], b1 = bias[col + 1];
            float v00 = fmaxf(acc[m][nt][0] + b0, 0.f), v01 = fmaxf(acc[m][nt][1] + b1, 0.f);
            float v10 = fmaxf(acc[m][nt][2] + b0, 0.f), v11 = fmaxf(acc[m][nt][3] + b1, 0.f);
            __nv_bfloat16 h0, l0, h1, l1;
            if (r1 < NN) {
                split2(v00, h0, l0); split2(v01, h1, l1);
                __nv_bfloat162 hh; hh.x = h0; hh.y = h1;
                __nv_bfloat162 ll; ll.x = l0; ll.y = l1;
                *(__nv_bfloat162*)(outH + (size_t)r1 * 128 + col) = hh;
                *(__nv_bfloat162*)(outL + (size_t)r1 * 128 + col) = ll;
            }
            if (r2 < NN) {
                split2(v10, h0, l0); split2(v11, h1, l1);
                __nv_bfloat162 hh; hh.x = h0; hh.y = h1;
                __nv_bfloat162 ll; ll.x = l0; ll.y = l1;
                *(__nv_bfloat162*)(outH + (size_t)r2 * 128 + col) = hh;
                *(__nv_bfloat162*)(outL + (size_t)r2 * 128 + col) = ll;
            }
        }
    }
}

// ---------------------------------------------------------------------------
// One-shot weight prep: transpose+split emb_w / rel_w / root_w, pack head_w.
// ---------------------------------------------------------------------------
constexpr int PW_EMB  = 256 * 128;          // 32768
constexpr int PW_REL  = 3 * 128 * 128;      // 49152
constexpr int PW_HEAD = 128 * 64;           // 8192
constexpr int PW_TOTAL = PW_EMB + 2 * PW_REL + PW_HEAD;  // 139264

__global__ void prep_weights(const float* __restrict__ emb_w,
                             const float* __restrict__ rel_w,
                             const float* __restrict__ root_w,
                             const float* __restrict__ head_w,
                             __nv_bfloat16* __restrict__ ewh, __nv_bfloat16* __restrict__ ewl,
                             __nv_bfloat16* __restrict__ rwh, __nv_bfloat16* __restrict__ rwl,
                             __nv_bfloat16* __restrict__ owh, __nv_bfloat16* __restrict__ owl,
                             float* __restrict__ hw)
{
    int i = blockIdx.x * blockDim.x + threadIdx.x;
    if (i >= PW_TOTAL) return;
    if (i < PW_EMB) {
        int k = i / 128, n = i % 128;
        __nv_bfloat16 h, l;
        split2(emb_w[i], h, l);
        ewh[n * 256 + k] = h;
        ewl[n * 256 + k] = l;
    } else if (i < PW_EMB + PW_REL) {
        int r = i - PW_EMB;
        int l0 = r / (128 * 128), rem = r % (128 * 128);
        int k = rem / 128, n = rem % 128;
        __nv_bfloat16 h, lo;
        split2(rel_w[r], h, lo);
        rwh[(size_t)l0 * 128 * 128 + n * 128 + k] = h;
        rwl[(size_t)l0 * 128 * 128 + n * 128 + k] = lo;
    } else if (i < PW_EMB + 2 * PW_REL) {
        int r = i - PW_EMB - PW_REL;
        int l0 = r / (128 * 128), rem = r % (128 * 128);
        int k = rem / 128, n = rem % 128;
        __nv_bfloat16 h, lo;
        split2(root_w[r], h, lo);
        owh[(size_t)l0 * 128 * 128 + n * 128 + k] = h;
        owl[(size_t)l0 * 128 * 128 + n * 128 + k] = lo;
    } else {
        int r = i - PW_EMB - 2 * PW_REL;
        int k = r / 64, c = r % 64;
        hw[r] = (c < 32) ? head_w[k * CLS + c] : head_w[(128 + k) * CLS + (c - 32)];
    }
}

// ---------------------------------------------------------------------------
// Head GEMM (fp32, FFMA2): C[M,64] = A[M,128] @ B[128,64]
// ---------------------------------------------------------------------------
#define FMA2(acc, a, b) asm("fma.rn.f32x2 %0, %1, %2, %0;" : "+l"(acc) : "l"(a), "l"(b))
__device__ __forceinline__ unsigned long long dup_f32(float x) {
    unsigned long long r;
    asm("mov.b64 %0, {%1, %1};" : "=l"(r) : "f"(x));
    return r;
}
__device__ __forceinline__ void unpack2(unsigned long long v, float& lo, float& hi) {
    asm("mov.b64 {%0, %1}, %2;" : "=f"(lo), "=f"(hi) : "l"(v));
}

__global__ void __launch_bounds__(256)
gemm_head(const float* __restrict__ A, const float* __restrict__ B,
          float* __restrict__ C, int M)
{
    __shared__ float As[16][128 + 4];
    __shared__ float Bs[16][64];

    const int tid  = threadIdx.x;
    const int row0 = blockIdx.x * 128;
    const int trow = (tid / 16) * 8;
    const int tcol = (tid % 16) * 4;

    unsigned long long acc[8][2];
#pragma unroll
    for (int i = 0; i < 8; i++) acc[i][0] = acc[i][1] = 0ULL;

    for (int k0 = 0; k0 < 128; k0 += 16) {
#pragma unroll
        for (int v = 0; v < 2; v++) {
            int vid = tid + v * 256;
            int r = vid >> 2, k = (vid & 3) * 4;
            float4 t = make_float4(0.f, 0.f, 0.f, 0.f);
            int gr = row0 + r;
            if (gr < M) t = *(const float4*)&A[(size_t)gr * 128 + k0 + k];
            As[k + 0][r] = t.x; As[k + 1][r] = t.y; As[k + 2][r] = t.z; As[k + 3][r] = t.w;
        }
        {
            int bk = tid >> 4, c = (tid & 15) * 4;
            *(float4*)&Bs[bk][c] = *(const float4*)&B[(size_t)(k0 + bk) * 64 + c];
        }
        __syncthreads();
#pragma unroll
        for (int kk = 0; kk < 16; kk++) {
            float a[8];
            *(float4*)&a[0] = *(const float4*)&As[kk][trow];
            *(float4*)&a[4] = *(const float4*)&As[kk][trow + 4];
            float4 b = *(const float4*)&Bs[kk][tcol];
            unsigned long long b01 = ((const unsigned long long*)&b)[0];
            unsigned long long b23 = ((const unsigned long long*)&b)[1];
#pragma unroll
            for (int i = 0; i < 8; i++) {
                unsigned long long aa = dup_f32(a[i]);
                FMA2(acc[i][0], aa, b01);
                FMA2(acc[i][1], aa, b23);
            }
        }
        __syncthreads();
    }
#pragma unroll
    for (int i = 0; i < 8; i++) {
        int gr = row0 + trow + i;
        if (gr >= M) continue;
        float l0, h0, l1, h1;
        unpack2(acc[i][0], l0, h0);
        unpack2(acc[i][1], l1, h1);
        *(float4*)&C[(size_t)gr * 64 + tcol] = make_float4(l0, h0, l1, h1);
    }
}

// ---------------------------------------------------------------------------
// CSR construction
// ---------------------------------------------------------------------------
__global__ void zero_off_kernel(int* __restrict__ off)
{
    int i = blockIdx.x * blockDim.x + threadIdx.x;
    if (i <= NN) off[i] = 0;
}
__global__ void hist_kernel(const int* __restrict__ ei, int* __restrict__ off)
{
    int e = blockIdx.x * blockDim.x + threadIdx.x;
    if (e >= NE) return;
    atomicAdd(&off[ei[NE + e] + 1], 1);
}
__global__ void __launch_bounds__(1024)
scan_kernel(int* __restrict__ off, int* __restrict__ cur)
{
    __shared__ int part[1024];
    const int tid = threadIdx.x;
    const int chunk = (NN + 1023) / 1024;
    int start = 1 + tid * chunk;
    int end = start + chunk; if (end > NN + 1) end = NN + 1;
    int s = 0;
    for (int i = start; i < end; i++) s += off[i];
    part[tid] = s;
    __syncthreads();
    for (int d = 1; d < 1024; d <<= 1) {
        int v = (tid >= d) ? part[tid - d] : 0;
        __syncthreads();
        part[tid] += v;
        __syncthreads();
    }
    int run = (tid == 0) ? 0 : part[tid - 1];
    for (int i = start; i < end; i++) { run += off[i]; off[i] = run; }
    __syncthreads();
    for (int i = tid; i < NN; i += 1024) cur[i] = off[i];
}
__global__ void fill_kernel(const int* __restrict__ ei, int* __restrict__ cur,
                            int* __restrict__ csr)
{
    int e = blockIdx.x * blockDim.x + threadIdx.x;
    if (e >= NE) return;
    int p = atomicAdd(&cur[ei[NE + e]], 1);
    csr[p] = ei[e];
}

// ---------------------------------------------------------------------------
// Aggregates: x[n] = relu(z[n] + sum y[src])   (warp per node, 2-way unroll)
// ---------------------------------------------------------------------------
__device__ __forceinline__ float4 agg_node(const float4* __restrict__ y4,
                                           const float4* __restrict__ z4,
                                           const int* __restrict__ csr,
                                           int node, int lane, int s, int e)
{
    float4 acc = z4[(size_t)node * 32 + lane];
    for (int b = s; b < e; b += 32) {
        int idx = b + lane;
        int mysrc = (idx < e) ? csr[idx] : 0;
        int cnt = e - b; if (cnt > 32) cnt = 32;
        int j = 0;
        for (; j + 2 <= cnt; j += 2) {
            int s0 = __shfl_sync(0xffffffffu, mysrc, j);
            int s1 = __shfl_sync(0xffffffffu, mysrc, j + 1);
            float4 v0 = y4[(size_t)s0 * 32 + lane];
            float4 v1 = y4[(size_t)s1 * 32 + lane];
            acc.x += v0.x + v1.x; acc.y += v0.y + v1.y;
            acc.z += v0.z + v1.z; acc.w += v0.w + v1.w;
        }
        if (j < cnt) {
            int s0 = __shfl_sync(0xffffffffu, mysrc, j);
            float4 v0 = y4[(size_t)s0 * 32 + lane];
            acc.x += v0.x; acc.y += v0.y; acc.z += v0.z; acc.w += v0.w;
        }
    }
    acc.x = fmaxf(acc.x, 0.f); acc.y = fmaxf(acc.y, 0.f);
    acc.z = fmaxf(acc.z, 0.f); acc.w = fmaxf(acc.w, 0.f);
    return acc;
}

__global__ void aggregate_split_kernel(const float4* __restrict__ y4,
                                       const float4* __restrict__ z4,
                                       __nv_bfloat16* __restrict__ xh,
                                       __nv_bfloat16* __restrict__ xl,
                                       const int* __restrict__ off,
                                       const int* __restrict__ csr)
{
    int node = (blockIdx.x * blockDim.x + threadIdx.x) >> 5;
    int lane = threadIdx.x & 31;
    if (node >= NN) return;
    float4 acc = agg_node(y4, z4, csr, node, lane, off[node], off[node + 1]);
    __nv_bfloat16 h0, l0, h1, l1, h2, l2, h3, l3;
    split2(acc.x, h0, l0); split2(acc.y, h1, l1);
    split2(acc.z, h2, l2); split2(acc.w, h3, l3);
    __nv_bfloat162 ha, hb, la, lb;
    ha.x = h0; ha.y = h1; hb.x = h2; hb.y = h3;
    la.x = l0; la.y = l1; lb.x = l2; lb.y = l3;
    size_t base = (size_t)node * 128 + lane * 4;
    *(__nv_bfloat162*)(xh + base)     = ha;
    *(__nv_bfloat162*)(xh + base + 2) = hb;
    *(__nv_bfloat162*)(xl + base)     = la;
    *(__nv_bfloat162*)(xl + base + 2) = lb;
}

__global__ void aggregate_f32_kernel(const float4* __restrict__ y4,
                                     const float4* __restrict__ z4,
                                     float4* __restrict__ x4,
                                     const int* __restrict__ off,
                                     const int* __restrict__ csr)
{
    int node = (blockIdx.x * blockDim.x + threadIdx.x) >> 5;
    int lane = threadIdx.x & 31;
    if (node >= NN) return;
    x4[(size_t)node * 32 + lane] =
        agg_node(y4, z4, csr, node, lane, off[node], off[node + 1]);
}

// ---------------------------------------------------------------------------
__global__ void edge_out_kernel(const float* __restrict__ fg,
                                const int* __restrict__ ei,
                                const float* __restrict__ head_b,
                                float* __restrict__ out)
{
    int warp = (blockIdx.x * blockDim.x + threadIdx.x) >> 5;
    int lane = threadIdx.x & 31;
    if (warp >= NE) return;
    int src = ei[warp];
    int dst = ei[NE + warp];
    float v = fg[(size_t)src * 64 + lane] + fg[(size_t)dst * 64 + 32 + lane] + head_b[lane];
    out[(size_t)warp * CLS + lane] = v;
}

// ---------------------------------------------------------------------------
extern "C" void kernel_launch(void* const* d_in, const int* in_sizes, int n_in,
                              void* d_out, int out_size)
{
    const float* obj    = (const float*)d_in[0];
    const int*   ei     = (const int*)d_in[1];   // int32 (JAX x64 disabled)
    const float* emb_w  = (const float*)d_in[2];
    const float* emb_b  = (const float*)d_in[3];
    const float* rel_w  = (const float*)d_in[4];
    const float* rel_b  = (const float*)d_in[5];
    const float* root_w = (const float*)d_in[6];
    const float* head_w = (const float*)d_in[7];
    const float* head_b = (const float*)d_in[8];
    float*       out    = (float*)d_out;

    float *x, *y, *z, *fg, *hw;
    int *off, *cur, *csr;
    __nv_bfloat16 *xh, *xl, *ewh, *ewl, *rwh, *rwl, *owh, *owl;
    cudaGetSymbolAddress((void**)&x,   g_x);
    cudaGetSymbolAddress((void**)&y,   g_y);
    cudaGetSymbolAddress((void**)&z,   g_z);
    cudaGetSymbolAddress((void**)&fg,  g_fg);
    cudaGetSymbolAddress((void**)&hw,  g_hw);
    cudaGetSymbolAddress((void**)&off, g_off);
    cudaGetSymbolAddress((void**)&cur, g_cur);
    cudaGetSymbolAddress((void**)&csr, g_csr);
    cudaGetSymbolAddress((void**)&xh,  g_xh);
    cudaGetSymbolAddress((void**)&xl,  g_xl);
    cudaGetSymbolAddress((void**)&ewh, g_ewh);
    cudaGetSymbolAddress((void**)&ewl, g_ewl);
    cudaGetSymbolAddress((void**)&rwh, g_rwh);
    cudaGetSymbolAddress((void**)&rwl, g_rwl);
    cudaGetSymbolAddress((void**)&owh, g_owh);
    cudaGetSymbolAddress((void**)&owl, g_owl);

    cudaFuncSetAttribute(gemm_emb,   cudaFuncAttributeMaxDynamicSharedMemorySize, GSM_SIZE);
    cudaFuncSetAttribute(gemm_layer, cudaFuncAttributeMaxDynamicSharedMemorySize, LSM_SIZE);

    const int gemm_gx   = (NN + 127) / 128;        // 391
    const int ne_blocks = (NE + 255) / 256;
    const int warp_blocks = (NE * 32 + 255) / 256;
    const int agg_blocks  = (NN * 32 + 255) / 256;

    // CSR build
    zero_off_kernel<<<(NN + 256) / 256, 256>>>(off);
    hist_kernel<<<ne_blocks, 256>>>(ei, off);
    scan_kernel<<<1, 1024>>>(off, cur);
    fill_kernel<<<ne_blocks, 256>>>(ei, cur, csr);

    // one-shot weight prep
    prep_weights<<<(PW_TOTAL + 255) / 256, 256>>>(
        emb_w, rel_w, root_w, head_w, ewh, ewl, rwh, rwl, owh, owl, hw);

    // embedding: x(split bf16) = relu(obj @ emb_w + emb_b) — obj split in staging
    gemm_emb<<<gemm_gx, 256, GSM_SIZE>>>(obj, ewh, ewl, emb_b, xh, xl);

    // 3 GraphConv layers
    for (int l = 0; l < NLAYERS; l++) {
        gemm_layer<<<gemm_gx, 256, LSM_SIZE>>>(
            xh, xl,
            rwh + (size_t)l * 128 * 128, rwl + (size_t)l * 128 * 128,
            owh + (size_t)l * 128 * 128, owl + (size_t)l * 128 * 128,
            rel_b + (size_t)l * 128, y, z);
        if (l < NLAYERS - 1)
            aggregate_split_kernel<<<agg_blocks, 256>>>(
                (const float4*)y, (const float4*)z, xh, xl, off, csr);
        else
            aggregate_f32_kernel<<<agg_blocks, 256>>>(
                (const float4*)y, (const float4*)z, (float4*)x, off, csr);
    }

    // edge head
    gemm_head<<<gemm_gx, 256>>>(x, hw, fg, NN);
    edge_out_kernel<<<warp_blocks, 256>>>(fg, ei, head_b, out);
}

// round 14
// speedup vs baseline: 2.9908x; 1.1680x over previous
#include <cuda_runtime.h>
#include <cuda_bf16.h>
#include <cstdint>

constexpr int NN   = 50000;   // nodes
constexpr int NE   = 600000;  // edges
constexpr int FEAT = 256;
constexpr int HID  = 128;
constexpr int CLS  = 32;
constexpr int NLAYERS = 3;

// ---------------- device scratch (no allocs allowed) ----------------
__device__ float g_x [NN * HID];          // fp32 node features (final layer)
__device__ float g_y [NN * HID];          // y = x @ rel_w
__device__ float g_z [NN * HID];          // z = x @ root_w + b
__device__ float g_fg[NN * 64];
__device__ float g_hw[128 * 64];
__device__ int   g_off[NN + 1];
__device__ int   g_cur[NN];
__device__ int   g_csr[NE];

__device__ __nv_bfloat16 g_xh[NN * HID];   // split x (hi)
__device__ __nv_bfloat16 g_xl[NN * HID];   // split x (lo)
__device__ __nv_bfloat16 g_ewh[128 * 256]; // emb_w^T hi  [N=128, K=256]
__device__ __nv_bfloat16 g_ewl[128 * 256];
__device__ __nv_bfloat16 g_rwh[3 * 128 * 128]; // rel_w^T
__device__ __nv_bfloat16 g_rwl[3 * 128 * 128];
__device__ __nv_bfloat16 g_owh[3 * 128 * 128]; // root_w^T
__device__ __nv_bfloat16 g_owl[3 * 128 * 128];

// ---------------- helpers ----------------
__device__ __forceinline__ uint32_t smem_u32(const void* p) {
    uint32_t a;
    asm("{ .reg .u64 t; cvta.to.shared.u64 t, %1; cvt.u32.u64 %0, t; }" : "=r"(a) : "l"(p));
    return a;
}
__device__ __forceinline__ void split2(float v, __nv_bfloat16& h, __nv_bfloat16& l) {
    h = __float2bfloat16_rn(v);
    l = __float2bfloat16_rn(v - __bfloat162float(h));
}
__device__ __forceinline__ void ldsm4(uint32_t* r, uint32_t addr) {
    asm volatile("ldmatrix.sync.aligned.m8n8.x4.shared.b16 {%0,%1,%2,%3}, [%4];"
        : "=r"(r[0]), "=r"(r[1]), "=r"(r[2]), "=r"(r[3]) : "r"(addr));
}
__device__ __forceinline__ void ldsm2(uint32_t* r, uint32_t addr) {
    asm volatile("ldmatrix.sync.aligned.m8n8.x2.shared.b16 {%0,%1}, [%2];"
        : "=r"(r[0]), "=r"(r[1]) : "r"(addr));
}
__device__ __forceinline__ void mma_bf16(float* c, const uint32_t* a, const uint32_t* b) {
    asm volatile(
        "mma.sync.aligned.m16n8k16.row.col.f32.bf16.bf16.f32 "
        "{%0,%1,%2,%3}, {%4,%5,%6,%7}, {%8,%9}, {%0,%1,%2,%3};"
        : "+f"(c[0]), "+f"(c[1]), "+f"(c[2]), "+f"(c[3])
        : "r"(a[0]), "r"(a[1]), "r"(a[2]), "r"(a[3]), "r"(b[0]), "r"(b[1]));
}

constexpr int KCH  = 128;
constexpr int KST  = KCH + 8;                 // padded smem stride (bf16)
constexpr int TILE_ELEMS = 128 * KST;         // 17408
constexpr int TILE_BYTES = TILE_ELEMS * 2;    // 34816
constexpr int GSM_SIZE   = 4 * TILE_BYTES;    // emb kernel: 4 tiles
constexpr int LSM_SIZE   = 6 * TILE_BYTES;    // fused layer kernel: 6 tiles (204KB)

// ---------------------------------------------------------------------------
// Fused layer GEMM (split-precision bf16 mma.sync):
//   Y = X @ rel_w           -> outY
//   Z = X @ root_w + bias   -> outZ
// ---------------------------------------------------------------------------
__global__ void __launch_bounds__(256)
gemm_layer(const __nv_bfloat16* __restrict__ Ah, const __nv_bfloat16* __restrict__ Al,
           const __nv_bfloat16* __restrict__ Rh, const __nv_bfloat16* __restrict__ Rl,
           const __nv_bfloat16* __restrict__ Oh, const __nv_bfloat16* __restrict__ Ol,
           const float* __restrict__ bias,
           float* __restrict__ outY, float* __restrict__ outZ)
{
    extern __shared__ __nv_bfloat16 sm[];
    __nv_bfloat16* sAh = sm;
    __nv_bfloat16* sAl = sm + TILE_ELEMS;
    __nv_bfloat16* sRh = sm + 2 * TILE_ELEMS;
    __nv_bfloat16* sRl = sm + 3 * TILE_ELEMS;
    __nv_bfloat16* sOh = sm + 4 * TILE_ELEMS;
    __nv_bfloat16* sOl = sm + 5 * TILE_ELEMS;

    const int tid  = threadIdx.x;
    const int warp = tid >> 5, lane = tid & 31;
    const int row0 = blockIdx.x * 128;
    const int rows = NN - row0;
    const int wm = (warp >> 1) * 32;
    const int wn = (warp & 1) * 64;

#pragma unroll
    for (int v = 0; v < 8; v++) {
        int i = tid + v * 256;
        int r = i >> 4, c = (i & 15) * 8;
        uint4 t = make_uint4(0u, 0u, 0u, 0u);
        uint4 u = make_uint4(0u, 0u, 0u, 0u);
        if (r < rows) {
            t = *(const uint4*)(Ah + (size_t)(row0 + r) * 128 + c);
            u = *(const uint4*)(Al + (size_t)(row0 + r) * 128 + c);
        }
        *(uint4*)(sAh + r * KST + c) = t;
        *(uint4*)(sAl + r * KST + c) = u;
        *(uint4*)(sRh + r * KST + c) = *(const uint4*)(Rh + (size_t)r * 128 + c);
        *(uint4*)(sRl + r * KST + c) = *(const uint4*)(Rl + (size_t)r * 128 + c);
        *(uint4*)(sOh + r * KST + c) = *(const uint4*)(Oh + (size_t)r * 128 + c);
        *(uint4*)(sOl + r * KST + c) = *(const uint4*)(Ol + (size_t)r * 128 + c);
    }
    __syncthreads();

    float accY[2][8][4], accZ[2][8][4];
#pragma unroll
    for (int m = 0; m < 2; m++)
#pragma unroll
        for (int nt = 0; nt < 8; nt++)
#pragma unroll
            for (int j = 0; j < 4; j++) { accY[m][nt][j] = 0.f; accZ[m][nt][j] = 0.f; }

    const uint32_t uAh = smem_u32(sAh), uAl = smem_u32(sAl);
    const uint32_t uRh = smem_u32(sRh), uRl = smem_u32(sRl);
    const uint32_t uOh = smem_u32(sOh), uOl = smem_u32(sOl);

    const int rin  = lane & 7;
    const int quad = lane >> 3;
    const int a_radd = (quad & 1) * 8 + rin;
    const int a_cadd = (quad >> 1) * 16;
    const int b_l16  = lane & 15;
    const int b_radd = b_l16 & 7;
    const int b_cadd = (b_l16 >> 3) * 16;

#pragma unroll
    for (int ks = 0; ks < 8; ks++) {
        uint32_t afh[2][4], afl[2][4];
#pragma unroll
        for (int m = 0; m < 2; m++) {
            uint32_t off = (uint32_t)(wm + m * 16 + a_radd) * (KST * 2)
                         + (uint32_t)(ks * 32 + a_cadd);
            ldsm4(afh[m], uAh + off);
            ldsm4(afl[m], uAl + off);
        }
#pragma unroll
        for (int nt = 0; nt < 8; nt++) {
            uint32_t off = (uint32_t)(wn + nt * 8 + b_radd) * (KST * 2)
                         + (uint32_t)(ks * 32 + b_cadd);
            uint32_t rh[2], rl[2], oh[2], ol[2];
            ldsm2(rh, uRh + off);
            ldsm2(rl, uRl + off);
            ldsm2(oh, uOh + off);
            ldsm2(ol, uOl + off);
#pragma unroll
            for (int m = 0; m < 2; m++) {
                mma_bf16(accY[m][nt], afh[m], rh);
                mma_bf16(accY[m][nt], afl[m], rh);
                mma_bf16(accY[m][nt], afh[m], rl);
                mma_bf16(accZ[m][nt], afh[m], oh);
                mma_bf16(accZ[m][nt], afl[m], oh);
                mma_bf16(accZ[m][nt], afh[m], ol);
            }
        }
    }

    const int g = lane >> 2, tig = lane & 3;
#pragma unroll
    for (int m = 0; m < 2; m++) {
#pragma unroll
        for (int nt = 0; nt < 8; nt++) {
            int col = wn + nt * 8 + 2 * tig;
            int r1 = row0 + wm + m * 16 + g;
            int r2 = r1 + 8;
            float b0 = bias[col], b1 = bias[col + 1];
            if (r1 < NN) {
                *(float2*)(outY + (size_t)r1 * 128 + col) =
                    make_float2(accY[m][nt][0], accY[m][nt][1]);
                *(float2*)(outZ + (size_t)r1 * 128 + col) =
                    make_float2(accZ[m][nt][0] + b0, accZ[m][nt][1] + b1);
            }
            if (r2 < NN) {
                *(float2*)(outY + (size_t)r2 * 128 + col) =
                    make_float2(accY[m][nt][2], accY[m][nt][3]);
                *(float2*)(outZ + (size_t)r2 * 128 + col) =
                    make_float2(accZ[m][nt][2] + b0, accZ[m][nt][3] + b1);
            }
        }
    }
}

// ---------------------------------------------------------------------------
// Embedding GEMM (split bf16 mma.sync, K=256 in 2 chunks):
//   split(relu(obj @ emb_w + bias)) -> outH, outL
// A is fp32 obj; split done in staging.
// ---------------------------------------------------------------------------
__global__ void __launch_bounds__(256)
gemm_emb(const float* __restrict__ A,
         const __nv_bfloat16* __restrict__ Bh, const __nv_bfloat16* __restrict__ Bl,
         const float* __restrict__ bias,
         __nv_bfloat16* __restrict__ outH, __nv_bfloat16* __restrict__ outL)
{
    extern __shared__ __nv_bfloat16 sm[];
    __nv_bfloat16* sAh = sm;
    __nv_bfloat16* sAl = sm + TILE_ELEMS;
    __nv_bfloat16* sBh = sm + 2 * TILE_ELEMS;
    __nv_bfloat16* sBl = sm + 3 * TILE_ELEMS;

    const int tid  = threadIdx.x;
    const int warp = tid >> 5, lane = tid & 31;
    const int row0 = blockIdx.x * 128;
    const int rows = NN - row0;
    const int wm = (warp >> 1) * 32;
    const int wn = (warp & 1) * 64;
    const int K = 256;

    float acc[2][8][4];
#pragma unroll
    for (int m = 0; m < 2; m++)
#pragma unroll
        for (int nt = 0; nt < 8; nt++)
#pragma unroll
            for (int j = 0; j < 4; j++) acc[m][nt][j] = 0.f;

    const uint32_t uAh = smem_u32(sAh), uAl = smem_u32(sAl);
    const uint32_t uBh = smem_u32(sBh), uBl = smem_u32(sBl);

    const int rin  = lane & 7;
    const int quad = lane >> 3;
    const int a_radd = (quad & 1) * 8 + rin;
    const int a_cadd = (quad >> 1) * 16;
    const int b_l16  = lane & 15;
    const int b_radd = b_l16 & 7;
    const int b_cadd = (b_l16 >> 3) * 16;

    for (int kc = 0; kc < K; kc += KCH) {
        if (kc) __syncthreads();
#pragma unroll
        for (int v = 0; v < 16; v++) {
            int i = tid + v * 256;
            int r = i >> 5, c4 = (i & 31) * 4;
            float4 t = make_float4(0.f, 0.f, 0.f, 0.f);
            if (r < rows)
                t = *(const float4*)(A + (size_t)(row0 + r) * K + kc + c4);
            __nv_bfloat16 h0, l0, h1, l1, h2, l2, h3, l3;
            split2(t.x, h0, l0); split2(t.y, h1, l1);
            split2(t.z, h2, l2); split2(t.w, h3, l3);
            __nv_bfloat162 ha, hb, la, lb;
            ha.x = h0; ha.y = h1; hb.x = h2; hb.y = h3;
            la.x = l0; la.y = l1; lb.x = l2; lb.y = l3;
            *(__nv_bfloat162*)(sAh + r * KST + c4)     = ha;
            *(__nv_bfloat162*)(sAh + r * KST + c4 + 2) = hb;
            *(__nv_bfloat162*)(sAl + r * KST + c4)     = la;
            *(__nv_bfloat162*)(sAl + r * KST + c4 + 2) = lb;
        }
#pragma unroll
        for (int v = 0; v < 8; v++) {
            int i = tid + v * 256;
            int r = i >> 4, c = (i & 15) * 8;
            *(uint4*)(sBh + r * KST + c) = *(const uint4*)(Bh + (size_t)r * K + kc + c);
            *(uint4*)(sBl + r * KST + c) = *(const uint4*)(Bl + (size_t)r * K + kc + c);
        }
        __syncthreads();

#pragma unroll
        for (int ks = 0; ks < 8; ks++) {
            uint32_t afh[2][4], afl[2][4];
#pragma unroll
            for (int m = 0; m < 2; m++) {
                uint32_t off = (uint32_t)(wm + m * 16 + a_radd) * (KST * 2)
                             + (uint32_t)(ks * 32 + a_cadd);
                ldsm4(afh[m], uAh + off);
                ldsm4(afl[m], uAl + off);
            }
#pragma unroll
            for (int nt = 0; nt < 8; nt++) {
                uint32_t bh[2], bl[2];
                uint32_t off = (uint32_t)(wn + nt * 8 + b_radd) * (KST * 2)
                             + (uint32_t)(ks * 32 + b_cadd);
                ldsm2(bh, uBh + off);
                ldsm2(bl, uBl + off);
#pragma unroll
                for (int m = 0; m < 2; m++) {
                    mma_bf16(acc[m][nt], afh[m], bh);
                    mma_bf16(acc[m][nt], afl[m], bh);
                    mma_bf16(acc[m][nt], afh[m], bl);
                }
            }
        }
    }

    const int g = lane >> 2, tig = lane & 3;
#pragma unroll
    for (int m = 0; m < 2; m++) {
#pragma unroll
        for (int nt = 0; nt < 8; nt++) {
            int col = wn + nt * 8 + 2 * tig;
            int r1 = row0 + wm + m * 16 + g;
            int r2 = r1 + 8;
            float b0 = bias[col], b1 = bias[col + 1];
            float v00 = fmaxf(acc[m][nt][0] + b0, 0.f), v01 = fmaxf(acc[m][nt][1] + b1, 0.f);
            float v10 = fmaxf(acc[m][nt][2] + b0, 0.f), v11 = fmaxf(acc[m][nt][3] + b1, 0.f);
            __nv_bfloat16 h0, l0, h1, l1;
            if (r1 < NN) {
                split2(v00, h0, l0); split2(v01, h1, l1);
                __nv_bfloat162 hh; hh.x = h0; hh.y = h1;
                __nv_bfloat162 ll; ll.x = l0; ll.y = l1;
                *(__nv_bfloat162*)(outH + (size_t)r1 * 128 + col) = hh;
                *(__nv_bfloat162*)(outL + (size_t)r1 * 128 + col) = ll;
            }
            if (r2 < NN) {
                split2(v10, h0, l0); split2(v11, h1, l1);
                __nv_bfloat162 hh; hh.x = h0; hh.y = h1;
                __nv_bfloat162 ll; ll.x = l0; ll.y = l1;
                *(__nv_bfloat162*)(outH + (size_t)r2 * 128 + col) = hh;
                *(__nv_bfloat162*)(outL + (size_t)r2 * 128 + col) = ll;
            }
        }
    }
}

// ---------------------------------------------------------------------------
// One-shot weight prep: transpose+split emb_w / rel_w / root_w, pack head_w.
// ---------------------------------------------------------------------------
constexpr int PW_EMB  = 256 * 128;
constexpr int PW_REL  = 3 * 128 * 128;
constexpr int PW_HEAD = 128 * 64;
constexpr int PW_TOTAL = PW_EMB + 2 * PW_REL + PW_HEAD;

__global__ void prep_weights(const float* __restrict__ emb_w,
                             const float* __restrict__ rel_w,
                             const float* __restrict__ root_w,
                             const float* __restrict__ head_w,
                             __nv_bfloat16* __restrict__ ewh, __nv_bfloat16* __restrict__ ewl,
                             __nv_bfloat16* __restrict__ rwh, __nv_bfloat16* __restrict__ rwl,
                             __nv_bfloat16* __restrict__ owh, __nv_bfloat16* __restrict__ owl,
                             float* __restrict__ hw)
{
    int i = blockIdx.x * blockDim.x + threadIdx.x;
    if (i >= PW_TOTAL) return;
    if (i < PW_EMB) {
        int k = i / 128, n = i % 128;
        __nv_bfloat16 h, l;
        split2(emb_w[i], h, l);
        ewh[n * 256 + k] = h;
        ewl[n * 256 + k] = l;
    } else if (i < PW_EMB + PW_REL) {
        int r = i - PW_EMB;
        int l0 = r / (128 * 128), rem = r % (128 * 128);
        int k = rem / 128, n = rem % 128;
        __nv_bfloat16 h, lo;
        split2(rel_w[r], h, lo);
        rwh[(size_t)l0 * 128 * 128 + n * 128 + k] = h;
        rwl[(size_t)l0 * 128 * 128 + n * 128 + k] = lo;
    } else if (i < PW_EMB + 2 * PW_REL) {
        int r = i - PW_EMB - PW_REL;
        int l0 = r / (128 * 128), rem = r % (128 * 128);
        int k = rem / 128, n = rem % 128;
        __nv_bfloat16 h, lo;
        split2(root_w[r], h, lo);
        owh[(size_t)l0 * 128 * 128 + n * 128 + k] = h;
        owl[(size_t)l0 * 128 * 128 + n * 128 + k] = lo;
    } else {
        int r = i - PW_EMB - 2 * PW_REL;
        int k = r / 64, c = r % 64;
        hw[r] = (c < 32) ? head_w[k * CLS + c] : head_w[(128 + k) * CLS + (c - 32)];
    }
}

// ---------------------------------------------------------------------------
// Head GEMM (fp32, FFMA2): C[M,64] = A[M,128] @ B[128,64]
// ---------------------------------------------------------------------------
#define FMA2(acc, a, b) asm("fma.rn.f32x2 %0, %1, %2, %0;" : "+l"(acc) : "l"(a), "l"(b))
__device__ __forceinline__ unsigned long long dup_f32(float x) {
    unsigned long long r;
    asm("mov.b64 %0, {%1, %1};" : "=l"(r) : "f"(x));
    return r;
}
__device__ __forceinline__ void unpack2(unsigned long long v, float& lo, float& hi) {
    asm("mov.b64 {%0, %1}, %2;" : "=f"(lo), "=f"(hi) : "l"(v));
}

__global__ void __launch_bounds__(256)
gemm_head(const float* __restrict__ A, const float* __restrict__ B,
          float* __restrict__ C, int M)
{
    __shared__ float As[16][128 + 4];
    __shared__ float Bs[16][64];

    const int tid  = threadIdx.x;
    const int row0 = blockIdx.x * 128;
    const int trow = (tid / 16) * 8;
    const int tcol = (tid % 16) * 4;

    unsigned long long acc[8][2];
#pragma unroll
    for (int i = 0; i < 8; i++) acc[i][0] = acc[i][1] = 0ULL;

    for (int k0 = 0; k0 < 128; k0 += 16) {
#pragma unroll
        for (int v = 0; v < 2; v++) {
            int vid = tid + v * 256;
            int r = vid >> 2, k = (vid & 3) * 4;
            float4 t = make_float4(0.f, 0.f, 0.f, 0.f);
            int gr = row0 + r;
            if (gr < M) t = *(const float4*)&A[(size_t)gr * 128 + k0 + k];
            As[k + 0][r] = t.x; As[k + 1][r] = t.y; As[k + 2][r] = t.z; As[k + 3][r] = t.w;
        }
        {
            int bk = tid >> 4, c = (tid & 15) * 4;
            *(float4*)&Bs[bk][c] = *(const float4*)&B[(size_t)(k0 + bk) * 64 + c];
        }
        __syncthreads();
#pragma unroll
        for (int kk = 0; kk < 16; kk++) {
            float a[8];
            *(float4*)&a[0] = *(const float4*)&As[kk][trow];
            *(float4*)&a[4] = *(const float4*)&As[kk][trow + 4];
            float4 b = *(const float4*)&Bs[kk][tcol];
            unsigned long long b01 = ((const unsigned long long*)&b)[0];
            unsigned long long b23 = ((const unsigned long long*)&b)[1];
#pragma unroll
            for (int i = 0; i < 8; i++) {
                unsigned long long aa = dup_f32(a[i]);
                FMA2(acc[i][0], aa, b01);
                FMA2(acc[i][1], aa, b23);
            }
        }
        __syncthreads();
    }
#pragma unroll
    for (int i = 0; i < 8; i++) {
        int gr = row0 + trow + i;
        if (gr >= M) continue;
        float l0, h0, l1, h1;
        unpack2(acc[i][0], l0, h0);
        unpack2(acc[i][1], l1, h1);
        *(float4*)&C[(size_t)gr * 64 + tcol] = make_float4(l0, h0, l1, h1);
    }
}

// ---------------------------------------------------------------------------
// CSR construction
// ---------------------------------------------------------------------------
__global__ void zero_off_kernel(int* __restrict__ off)
{
    int i = blockIdx.x * blockDim.x + threadIdx.x;
    if (i <= NN) off[i] = 0;
}
__global__ void hist_kernel(const int* __restrict__ ei, int* __restrict__ off)
{
    int e = blockIdx.x * blockDim.x + threadIdx.x;
    if (e >= NE) return;
    atomicAdd(&off[ei[NE + e] + 1], 1);
}
__global__ void __launch_bounds__(1024)
scan_kernel(int* __restrict__ off, int* __restrict__ cur)
{
    __shared__ int part[1024];
    const int tid = threadIdx.x;
    const int chunk = (NN + 1023) / 1024;
    int start = 1 + tid * chunk;
    int end = start + chunk; if (end > NN + 1) end = NN + 1;
    int s = 0;
    for (int i = start; i < end; i++) s += off[i];
    part[tid] = s;
    __syncthreads();
    for (int d = 1; d < 1024; d <<= 1) {
        int v = (tid >= d) ? part[tid - d] : 0;
        __syncthreads();
        part[tid] += v;
        __syncthreads();
    }
    int run = (tid == 0) ? 0 : part[tid - 1];
    for (int i = start; i < end; i++) { run += off[i]; off[i] = run; }
    __syncthreads();
    for (int i = tid; i < NN; i += 1024) cur[i] = off[i];
}
__global__ void fill_kernel(const int* __restrict__ ei, int* __restrict__ cur,
                            int* __restrict__ csr)
{
    int e = blockIdx.x * blockDim.x + threadIdx.x;
    if (e >= NE) return;
    int p = atomicAdd(&cur[ei[NE + e]], 1);
    csr[p] = ei[e];
}

// ---------------------------------------------------------------------------
// Aggregates: x[n] = relu(z[n] + sum y[src])   (warp per node, 4-way unroll)
// ---------------------------------------------------------------------------
__device__ __forceinline__ float4 agg_node(const float4* __restrict__ y4,
                                           const float4* __restrict__ z4,
                                           const int* __restrict__ csr,
                                           int node, int lane, int s, int e)
{
    float4 acc = z4[(size_t)node * 32 + lane];
    for (int b = s; b < e; b += 32) {
        int idx = b + lane;
        int mysrc = (idx < e) ? csr[idx] : 0;
        int cnt = e - b; if (cnt > 32) cnt = 32;
        int j = 0;
        for (; j + 4 <= cnt; j += 4) {
            int s0 = __shfl_sync(0xffffffffu, mysrc, j);
            int s1 = __shfl_sync(0xffffffffu, mysrc, j + 1);
            int s2 = __shfl_sync(0xffffffffu, mysrc, j + 2);
            int s3 = __shfl_sync(0xffffffffu, mysrc, j + 3);
            float4 v0 = y4[(size_t)s0 * 32 + lane];
            float4 v1 = y4[(size_t)s1 * 32 + lane];
            float4 v2 = y4[(size_t)s2 * 32 + lane];
            float4 v3 = y4[(size_t)s3 * 32 + lane];
            acc.x += (v0.x + v1.x) + (v2.x + v3.x);
            acc.y += (v0.y + v1.y) + (v2.y + v3.y);
            acc.z += (v0.z + v1.z) + (v2.z + v3.z);
            acc.w += (v0.w + v1.w) + (v2.w + v3.w);
        }
        for (; j < cnt; j++) {
            int s0 = __shfl_sync(0xffffffffu, mysrc, j);
            float4 v0 = y4[(size_t)s0 * 32 + lane];
            acc.x += v0.x; acc.y += v0.y; acc.z += v0.z; acc.w += v0.w;
        }
    }
    acc.x = fmaxf(acc.x, 0.f); acc.y = fmaxf(acc.y, 0.f);
    acc.z = fmaxf(acc.z, 0.f); acc.w = fmaxf(acc.w, 0.f);
    return acc;
}

__global__ void aggregate_split_kernel(const float4* __restrict__ y4,
                                       const float4* __restrict__ z4,
                                       __nv_bfloat16* __restrict__ xh,
                                       __nv_bfloat16* __restrict__ xl,
                                       const int* __restrict__ off,
                                       const int* __restrict__ csr)
{
    int node = (blockIdx.x * blockDim.x + threadIdx.x) >> 5;
    int lane = threadIdx.x & 31;
    if (node >= NN) return;
    float4 acc = agg_node(y4, z4, csr, node, lane, off[node], off[node + 1]);
    __nv_bfloat16 h0, l0, h1, l1, h2, l2, h3, l3;
    split2(acc.x, h0, l0); split2(acc.y, h1, l1);
    split2(acc.z, h2, l2); split2(acc.w, h3, l3);
    __nv_bfloat162 ha, hb, la, lb;
    ha.x = h0; ha.y = h1; hb.x = h2; hb.y = h3;
    la.x = l0; la.y = l1; lb.x = l2; lb.y = l3;
    size_t base = (size_t)node * 128 + lane * 4;
    *(__nv_bfloat162*)(xh + base)     = ha;
    *(__nv_bfloat162*)(xh + base + 2) = hb;
    *(__nv_bfloat162*)(xl + base)     = la;
    *(__nv_bfloat162*)(xl + base + 2) = lb;
}

__global__ void aggregate_f32_kernel(const float4* __restrict__ y4,
                                     const float4* __restrict__ z4,
                                     float4* __restrict__ x4,
                                     const int* __restrict__ off,
                                     const int* __restrict__ csr)
{
    int node = (blockIdx.x * blockDim.x + threadIdx.x) >> 5;
    int lane = threadIdx.x & 31;
    if (node >= NN) return;
    x4[(size_t)node * 32 + lane] =
        agg_node(y4, z4, csr, node, lane, off[node], off[node + 1]);
}

// ---------------------------------------------------------------------------
__global__ void edge_out_kernel(const float* __restrict__ fg,
                                const int* __restrict__ ei,
                                const float* __restrict__ head_b,
                                float* __restrict__ out)
{
    int warp = (blockIdx.x * blockDim.x + threadIdx.x) >> 5;
    int lane = threadIdx.x & 31;
    if (warp >= NE) return;
    int src = ei[warp];
    int dst = ei[NE + warp];
    float v = fg[(size_t)src * 64 + lane] + fg[(size_t)dst * 64 + 32 + lane] + head_b[lane];
    out[(size_t)warp * CLS + lane] = v;
}

// ---------------------------------------------------------------------------
extern "C" void kernel_launch(void* const* d_in, const int* in_sizes, int n_in,
                              void* d_out, int out_size)
{
    const float* obj    = (const float*)d_in[0];
    const int*   ei     = (const int*)d_in[1];   // int32 (JAX x64 disabled)
    const float* emb_w  = (const float*)d_in[2];
    const float* emb_b  = (const float*)d_in[3];
    const float* rel_w  = (const float*)d_in[4];
    const float* rel_b  = (const float*)d_in[5];
    const float* root_w = (const float*)d_in[6];
    const float* head_w = (const float*)d_in[7];
    const float* head_b = (const float*)d_in[8];
    float*       out    = (float*)d_out;

    float *x, *y, *z, *fg, *hw;
    int *off, *cur, *csr;
    __nv_bfloat16 *xh, *xl, *ewh, *ewl, *rwh, *rwl, *owh, *owl;
    cudaGetSymbolAddress((void**)&x,   g_x);
    cudaGetSymbolAddress((void**)&y,   g_y);
    cudaGetSymbolAddress((void**)&z,   g_z);
    cudaGetSymbolAddress((void**)&fg,  g_fg);
    cudaGetSymbolAddress((void**)&hw,  g_hw);
    cudaGetSymbolAddress((void**)&off, g_off);
    cudaGetSymbolAddress((void**)&cur, g_cur);
    cudaGetSymbolAddress((void**)&csr, g_csr);
    cudaGetSymbolAddress((void**)&xh,  g_xh);
    cudaGetSymbolAddress((void**)&xl,  g_xl);
    cudaGetSymbolAddress((void**)&ewh, g_ewh);
    cudaGetSymbolAddress((void**)&ewl, g_ewl);
    cudaGetSymbolAddress((void**)&rwh, g_rwh);
    cudaGetSymbolAddress((void**)&rwl, g_rwl);
    cudaGetSymbolAddress((void**)&owh, g_owh);
    cudaGetSymbolAddress((void**)&owl, g_owl);

    cudaFuncSetAttribute(gemm_emb,   cudaFuncAttributeMaxDynamicSharedMemorySize, GSM_SIZE);
    cudaFuncSetAttribute(gemm_layer, cudaFuncAttributeMaxDynamicSharedMemorySize, LSM_SIZE);

    // one-time stream/event resources (resources, not cached results)
    static cudaStream_t s_csr = nullptr;
    static cudaEvent_t  ev_fork = nullptr, ev_csr = nullptr;
    if (!s_csr) {
        cudaStreamCreateWithFlags(&s_csr, cudaStreamNonBlocking);
        cudaEventCreateWithFlags(&ev_fork, cudaEventDisableTiming);
        cudaEventCreateWithFlags(&ev_csr,  cudaEventDisableTiming);
    }

    const int gemm_gx   = (NN + 127) / 128;        // 391
    const int ne_blocks = (NE + 255) / 256;
    const int warp_blocks = (NE * 32 + 255) / 256;
    const int agg_blocks  = (NN * 32 + 255) / 256;

    // weight prep first (emb GEMM depends on it, same stream)
    prep_weights<<<(PW_TOTAL + 255) / 256, 256>>>(
        emb_w, rel_w, root_w, head_w, ewh, ewl, rwh, rwl, owh, owl, hw);

    // fork: CSR build runs concurrently with emb + layer-0 GEMMs
    cudaEventRecord(ev_fork, 0);
    cudaStreamWaitEvent(s_csr, ev_fork, 0);
    zero_off_kernel<<<(NN + 256) / 256, 256, 0, s_csr>>>(off);
    hist_kernel<<<ne_blocks, 256, 0, s_csr>>>(ei, off);
    scan_kernel<<<1, 1024, 0, s_csr>>>(off, cur);
    fill_kernel<<<ne_blocks, 256, 0, s_csr>>>(ei, cur, csr);
    cudaEventRecord(ev_csr, s_csr);

    // embedding: x(split bf16) = relu(obj @ emb_w + emb_b)
    gemm_emb<<<gemm_gx, 256, GSM_SIZE>>>(obj, ewh, ewl, emb_b, xh, xl);

    // layer 0 GEMM (doesn't need CSR)
    gemm_layer<<<gemm_gx, 256, LSM_SIZE>>>(
        xh, xl, rwh, rwl, owh, owl, rel_b, y, z);

    // join: aggregates need CSR
    cudaStreamWaitEvent(0, ev_csr, 0);

    aggregate_split_kernel<<<agg_blocks, 256>>>(
        (const float4*)y, (const float4*)z, xh, xl, off, csr);

    for (int l = 1; l < NLAYERS; l++) {
        gemm_layer<<<gemm_gx, 256, LSM_SIZE>>>(
            xh, xl,
            rwh + (size_t)l * 128 * 128, rwl + (size_t)l * 128 * 128,
            owh + (size_t)l * 128 * 128, owl + (size_t)l * 128 * 128,
            rel_b + (size_t)l * 128, y, z);
        if (l < NLAYERS - 1)
            aggregate_split_kernel<<<agg_blocks, 256>>>(
                (const float4*)y, (const float4*)z, xh, xl, off, csr);
        else
            aggregate_f32_kernel<<<agg_blocks, 256>>>(
                (const float4*)y, (const float4*)z, (float4*)x, off, csr);
    }

    // edge head
    gemm_head<<<gemm_gx, 256>>>(x, hw, fg, NN);
    edge_out_kernel<<<warp_blocks, 256>>>(fg, ei, head_b, out);
}

// round 15
// speedup vs baseline: 3.0549x; 1.0214x over previous
#include <cuda_runtime.h>
#include <cuda_bf16.h>
#include <cstdint>

constexpr int NN   = 50000;   // nodes
constexpr int NE   = 600000;  // edges
constexpr int FEAT = 256;
constexpr int HID  = 128;
constexpr int CLS  = 32;
constexpr int NLAYERS = 3;

// ---------------- device scratch (no allocs allowed) ----------------
__device__ float g_x [NN * HID];
__device__ float g_y [NN * HID];
__device__ float g_z [NN * HID];
__device__ float g_fg[NN * 64];
__device__ float g_hw[128 * 64];
__device__ int   g_off[NN + 1];
__device__ int   g_cur[NN];
__device__ int   g_csr[NE];

constexpr int SCAN_BLK = 512;
constexpr int SCAN_N   = NN + 1;                                  // 50001
constexpr int SCAN_NB  = (SCAN_N + SCAN_BLK - 1) / SCAN_BLK;      // 98
__device__ int g_bsum[SCAN_NB];

__device__ __nv_bfloat16 g_xh[NN * HID];
__device__ __nv_bfloat16 g_xl[NN * HID];
__device__ __nv_bfloat16 g_ewh[128 * 256];
__device__ __nv_bfloat16 g_ewl[128 * 256];
__device__ __nv_bfloat16 g_rwh[3 * 128 * 128];
__device__ __nv_bfloat16 g_rwl[3 * 128 * 128];
__device__ __nv_bfloat16 g_owh[3 * 128 * 128];
__device__ __nv_bfloat16 g_owl[3 * 128 * 128];

// ---------------- helpers ----------------
__device__ __forceinline__ uint32_t smem_u32(const void* p) {
    uint32_t a;
    asm("{ .reg .u64 t; cvta.to.shared.u64 t, %1; cvt.u32.u64 %0, t; }" : "=r"(a) : "l"(p));
    return a;
}
__device__ __forceinline__ void split2(float v, __nv_bfloat16& h, __nv_bfloat16& l) {
    h = __float2bfloat16_rn(v);
    l = __float2bfloat16_rn(v - __bfloat162float(h));
}
__device__ __forceinline__ void ldsm4(uint32_t* r, uint32_t addr) {
    asm volatile("ldmatrix.sync.aligned.m8n8.x4.shared.b16 {%0,%1,%2,%3}, [%4];"
        : "=r"(r[0]), "=r"(r[1]), "=r"(r[2]), "=r"(r[3]) : "r"(addr));
}
__device__ __forceinline__ void ldsm2(uint32_t* r, uint32_t addr) {
    asm volatile("ldmatrix.sync.aligned.m8n8.x2.shared.b16 {%0,%1}, [%2];"
        : "=r"(r[0]), "=r"(r[1]) : "r"(addr));
}
__device__ __forceinline__ void mma_bf16(float* c, const uint32_t* a, const uint32_t* b) {
    asm volatile(
        "mma.sync.aligned.m16n8k16.row.col.f32.bf16.bf16.f32 "
        "{%0,%1,%2,%3}, {%4,%5,%6,%7}, {%8,%9}, {%0,%1,%2,%3};"
        : "+f"(c[0]), "+f"(c[1]), "+f"(c[2]), "+f"(c[3])
        : "r"(a[0]), "r"(a[1]), "r"(a[2]), "r"(a[3]), "r"(b[0]), "r"(b[1]));
}

constexpr int KCH  = 128;
constexpr int KST  = KCH + 8;
constexpr int TILE_ELEMS = 128 * KST;
constexpr int TILE_BYTES = TILE_ELEMS * 2;
constexpr int GSM_SIZE   = 4 * TILE_BYTES;
constexpr int LSM_SIZE   = 6 * TILE_BYTES;

// ---------------------------------------------------------------------------
// Fused layer GEMM (split-precision bf16 mma.sync)
// ---------------------------------------------------------------------------
__global__ void __launch_bounds__(256)
gemm_layer(const __nv_bfloat16* __restrict__ Ah, const __nv_bfloat16* __restrict__ Al,
           const __nv_bfloat16* __restrict__ Rh, const __nv_bfloat16* __restrict__ Rl,
           const __nv_bfloat16* __restrict__ Oh, const __nv_bfloat16* __restrict__ Ol,
           const float* __restrict__ bias,
           float* __restrict__ outY, float* __restrict__ outZ)
{
    extern __shared__ __nv_bfloat16 sm[];
    __nv_bfloat16* sAh = sm;
    __nv_bfloat16* sAl = sm + TILE_ELEMS;
    __nv_bfloat16* sRh = sm + 2 * TILE_ELEMS;
    __nv_bfloat16* sRl = sm + 3 * TILE_ELEMS;
    __nv_bfloat16* sOh = sm + 4 * TILE_ELEMS;
    __nv_bfloat16* sOl = sm + 5 * TILE_ELEMS;

    const int tid  = threadIdx.x;
    const int warp = tid >> 5, lane = tid & 31;
    const int row0 = blockIdx.x * 128;
    const int rows = NN - row0;
    const int wm = (warp >> 1) * 32;
    const int wn = (warp & 1) * 64;

#pragma unroll
    for (int v = 0; v < 8; v++) {
        int i = tid + v * 256;
        int r = i >> 4, c = (i & 15) * 8;
        uint4 t = make_uint4(0u, 0u, 0u, 0u);
        uint4 u = make_uint4(0u, 0u, 0u, 0u);
        if (r < rows) {
            t = *(const uint4*)(Ah + (size_t)(row0 + r) * 128 + c);
            u = *(const uint4*)(Al + (size_t)(row0 + r) * 128 + c);
        }
        *(uint4*)(sAh + r * KST + c) = t;
        *(uint4*)(sAl + r * KST + c) = u;
        *(uint4*)(sRh + r * KST + c) = *(const uint4*)(Rh + (size_t)r * 128 + c);
        *(uint4*)(sRl + r * KST + c) = *(const uint4*)(Rl + (size_t)r * 128 + c);
        *(uint4*)(sOh + r * KST + c) = *(const uint4*)(Oh + (size_t)r * 128 + c);
        *(uint4*)(sOl + r * KST + c) = *(const uint4*)(Ol + (size_t)r * 128 + c);
    }
    __syncthreads();

    float accY[2][8][4], accZ[2][8][4];
#pragma unroll
    for (int m = 0; m < 2; m++)
#pragma unroll
        for (int nt = 0; nt < 8; nt++)
#pragma unroll
            for (int j = 0; j < 4; j++) { accY[m][nt][j] = 0.f; accZ[m][nt][j] = 0.f; }

    const uint32_t uAh = smem_u32(sAh), uAl = smem_u32(sAl);
    const uint32_t uRh = smem_u32(sRh), uRl = smem_u32(sRl);
    const uint32_t uOh = smem_u32(sOh), uOl = smem_u32(sOl);

    const int rin  = lane & 7;
    const int quad = lane >> 3;
    const int a_radd = (quad & 1) * 8 + rin;
    const int a_cadd = (quad >> 1) * 16;
    const int b_l16  = lane & 15;
    const int b_radd = b_l16 & 7;
    const int b_cadd = (b_l16 >> 3) * 16;

#pragma unroll
    for (int ks = 0; ks < 8; ks++) {
        uint32_t afh[2][4], afl[2][4];
#pragma unroll
        for (int m = 0; m < 2; m++) {
            uint32_t off = (uint32_t)(wm + m * 16 + a_radd) * (KST * 2)
                         + (uint32_t)(ks * 32 + a_cadd);
            ldsm4(afh[m], uAh + off);
            ldsm4(afl[m], uAl + off);
        }
#pragma unroll
        for (int nt = 0; nt < 8; nt++) {
            uint32_t off = (uint32_t)(wn + nt * 8 + b_radd) * (KST * 2)
                         + (uint32_t)(ks * 32 + b_cadd);
            uint32_t rh[2], rl[2], oh[2], ol[2];
            ldsm2(rh, uRh + off);
            ldsm2(rl, uRl + off);
            ldsm2(oh, uOh + off);
            ldsm2(ol, uOl + off);
#pragma unroll
            for (int m = 0; m < 2; m++) {
                mma_bf16(accY[m][nt], afh[m], rh);
                mma_bf16(accY[m][nt], afl[m], rh);
                mma_bf16(accY[m][nt], afh[m], rl);
                mma_bf16(accZ[m][nt], afh[m], oh);
                mma_bf16(accZ[m][nt], afl[m], oh);
                mma_bf16(accZ[m][nt], afh[m], ol);
            }
        }
    }

    const int g = lane >> 2, tig = lane & 3;
#pragma unroll
    for (int m = 0; m < 2; m++) {
#pragma unroll
        for (int nt = 0; nt < 8; nt++) {
            int col = wn + nt * 8 + 2 * tig;
            int r1 = row0 + wm + m * 16 + g;
            int r2 = r1 + 8;
            float b0 = bias[col], b1 = bias[col + 1];
            if (r1 < NN) {
                *(float2*)(outY + (size_t)r1 * 128 + col) =
                    make_float2(accY[m][nt][0], accY[m][nt][1]);
                *(float2*)(outZ + (size_t)r1 * 128 + col) =
                    make_float2(accZ[m][nt][0] + b0, accZ[m][nt][1] + b1);
            }
            if (r2 < NN) {
                *(float2*)(outY + (size_t)r2 * 128 + col) =
                    make_float2(accY[m][nt][2], accY[m][nt][3]);
                *(float2*)(outZ + (size_t)r2 * 128 + col) =
                    make_float2(accZ[m][nt][2] + b0, accZ[m][nt][3] + b1);
            }
        }
    }
}

// ---------------------------------------------------------------------------
// Embedding GEMM (split bf16 mma.sync, K=256 in 2 chunks)
// ---------------------------------------------------------------------------
__global__ void __launch_bounds__(256)
gemm_emb(const float* __restrict__ A,
         const __nv_bfloat16* __restrict__ Bh, const __nv_bfloat16* __restrict__ Bl,
         const float* __restrict__ bias,
         __nv_bfloat16* __restrict__ outH, __nv_bfloat16* __restrict__ outL)
{
    extern __shared__ __nv_bfloat16 sm[];
    __nv_bfloat16* sAh = sm;
    __nv_bfloat16* sAl = sm + TILE_ELEMS;
    __nv_bfloat16* sBh = sm + 2 * TILE_ELEMS;
    __nv_bfloat16* sBl = sm + 3 * TILE_ELEMS;

    const int tid  = threadIdx.x;
    const int warp = tid >> 5, lane = tid & 31;
    const int row0 = blockIdx.x * 128;
    const int rows = NN - row0;
    const int wm = (warp >> 1) * 32;
    const int wn = (warp & 1) * 64;
    const int K = 256;

    float acc[2][8][4];
#pragma unroll
    for (int m = 0; m < 2; m++)
#pragma unroll
        for (int nt = 0; nt < 8; nt++)
#pragma unroll
            for (int j = 0; j < 4; j++) acc[m][nt][j] = 0.f;

    const uint32_t uAh = smem_u32(sAh), uAl = smem_u32(sAl);
    const uint32_t uBh = smem_u32(sBh), uBl = smem_u32(sBl);

    const int rin  = lane & 7;
    const int quad = lane >> 3;
    const int a_radd = (quad & 1) * 8 + rin;
    const int a_cadd = (quad >> 1) * 16;
    const int b_l16  = lane & 15;
    const int b_radd = b_l16 & 7;
    const int b_cadd = (b_l16 >> 3) * 16;

    for (int kc = 0; kc < K; kc += KCH) {
        if (kc) __syncthreads();
#pragma unroll
        for (int v = 0; v < 16; v++) {
            int i = tid + v * 256;
            int r = i >> 5, c4 = (i & 31) * 4;
            float4 t = make_float4(0.f, 0.f, 0.f, 0.f);
            if (r < rows)
                t = *(const float4*)(A + (size_t)(row0 + r) * K + kc + c4);
            __nv_bfloat16 h0, l0, h1, l1, h2, l2, h3, l3;
            split2(t.x, h0, l0); split2(t.y, h1, l1);
            split2(t.z, h2, l2); split2(t.w, h3, l3);
            __nv_bfloat162 ha, hb, la, lb;
            ha.x = h0; ha.y = h1; hb.x = h2; hb.y = h3;
            la.x = l0; la.y = l1; lb.x = l2; lb.y = l3;
            *(__nv_bfloat162*)(sAh + r * KST + c4)     = ha;
            *(__nv_bfloat162*)(sAh + r * KST + c4 + 2) = hb;
            *(__nv_bfloat162*)(sAl + r * KST + c4)     = la;
            *(__nv_bfloat162*)(sAl + r * KST + c4 + 2) = lb;
        }
#pragma unroll
        for (int v = 0; v < 8; v++) {
            int i = tid + v * 256;
            int r = i >> 4, c = (i & 15) * 8;
            *(uint4*)(sBh + r * KST + c) = *(const uint4*)(Bh + (size_t)r * K + kc + c);
            *(uint4*)(sBl + r * KST + c) = *(const uint4*)(Bl + (size_t)r * K + kc + c);
        }
        __syncthreads();

#pragma unroll
        for (int ks = 0; ks < 8; ks++) {
            uint32_t afh[2][4], afl[2][4];
#pragma unroll
            for (int m = 0; m < 2; m++) {
                uint32_t off = (uint32_t)(wm + m * 16 + a_radd) * (KST * 2)
                             + (uint32_t)(ks * 32 + a_cadd);
                ldsm4(afh[m], uAh + off);
                ldsm4(afl[m], uAl + off);
            }
#pragma unroll
            for (int nt = 0; nt < 8; nt++) {
                uint32_t bh[2], bl[2];
                uint32_t off = (uint32_t)(wn + nt * 8 + b_radd) * (KST * 2)
                             + (uint32_t)(ks * 32 + b_cadd);
                ldsm2(bh, uBh + off);
                ldsm2(bl, uBl + off);
#pragma unroll
                for (int m = 0; m < 2; m++) {
                    mma_bf16(acc[m][nt], afh[m], bh);
                    mma_bf16(acc[m][nt], afl[m], bh);
                    mma_bf16(acc[m][nt], afh[m], bl);
                }
            }
        }
    }

    const int g = lane >> 2, tig = lane & 3;
#pragma unroll
    for (int m = 0; m < 2; m++) {
#pragma unroll
        for (int nt = 0; nt < 8; nt++) {
            int col = wn + nt * 8 + 2 * tig;
            int r1 = row0 + wm + m * 16 + g;
            int r2 = r1 + 8;
            float b0 = bias[col], b1 = bias[col + 1];
            float v00 = fmaxf(acc[m][nt][0] + b0, 0.f), v01 = fmaxf(acc[m][nt][1] + b1, 0.f);
            float v10 = fmaxf(acc[m][nt][2] + b0, 0.f), v11 = fmaxf(acc[m][nt][3] + b1, 0.f);
            __nv_bfloat16 h0, l0, h1, l1;
            if (r1 < NN) {
                split2(v00, h0, l0); split2(v01, h1, l1);
                __nv_bfloat162 hh; hh.x = h0; hh.y = h1;
                __nv_bfloat162 ll; ll.x = l0; ll.y = l1;
                *(__nv_bfloat162*)(outH + (size_t)r1 * 128 + col) = hh;
                *(__nv_bfloat162*)(outL + (size_t)r1 * 128 + col) = ll;
            }
            if (r2 < NN) {
                split2(v10, h0, l0); split2(v11, h1, l1);
                __nv_bfloat162 hh; hh.x = h0; hh.y = h1;
                __nv_bfloat162 ll; ll.x = l0; ll.y = l1;
                *(__nv_bfloat162*)(outH + (size_t)r2 * 128 + col) = hh;
                *(__nv_bfloat162*)(outL + (size_t)r2 * 128 + col) = ll;
            }
        }
    }
}

// ---------------------------------------------------------------------------
// One-shot weight prep
// ---------------------------------------------------------------------------
constexpr int PW_EMB  = 256 * 128;
constexpr int PW_REL  = 3 * 128 * 128;
constexpr int PW_HEAD = 128 * 64;
constexpr int PW_TOTAL = PW_EMB + 2 * PW_REL + PW_HEAD;

__global__ void prep_weights(const float* __restrict__ emb_w,
                             const float* __restrict__ rel_w,
                             const float* __restrict__ root_w,
                             const float* __restrict__ head_w,
                             __nv_bfloat16* __restrict__ ewh, __nv_bfloat16* __restrict__ ewl,
                             __nv_bfloat16* __restrict__ rwh, __nv_bfloat16* __restrict__ rwl,
                             __nv_bfloat16* __restrict__ owh, __nv_bfloat16* __restrict__ owl,
                             float* __restrict__ hw)
{
    int i = blockIdx.x * blockDim.x + threadIdx.x;
    if (i >= PW_TOTAL) return;
    if (i < PW_EMB) {
        int k = i / 128, n = i % 128;
        __nv_bfloat16 h, l;
        split2(emb_w[i], h, l);
        ewh[n * 256 + k] = h;
        ewl[n * 256 + k] = l;
    } else if (i < PW_EMB + PW_REL) {
        int r = i - PW_EMB;
        int l0 = r / (128 * 128), rem = r % (128 * 128);
        int k = rem / 128, n = rem % 128;
        __nv_bfloat16 h, lo;
        split2(rel_w[r], h, lo);
        rwh[(size_t)l0 * 128 * 128 + n * 128 + k] = h;
        rwl[(size_t)l0 * 128 * 128 + n * 128 + k] = lo;
    } else if (i < PW_EMB + 2 * PW_REL) {
        int r = i - PW_EMB - PW_REL;
        int l0 = r / (128 * 128), rem = r % (128 * 128);
        int k = rem / 128, n = rem % 128;
        __nv_bfloat16 h, lo;
        split2(root_w[r], h, lo);
        owh[(size_t)l0 * 128 * 128 + n * 128 + k] = h;
        owl[(size_t)l0 * 128 * 128 + n * 128 + k] = lo;
    } else {
        int r = i - PW_EMB - 2 * PW_REL;
        int k = r / 64, c = r % 64;
        hw[r] = (c < 32) ? head_w[k * CLS + c] : head_w[(128 + k) * CLS + (c - 32)];
    }
}

// ---------------------------------------------------------------------------
// Head GEMM (fp32, FFMA2)
// ---------------------------------------------------------------------------
#define FMA2(acc, a, b) asm("fma.rn.f32x2 %0, %1, %2, %0;" : "+l"(acc) : "l"(a), "l"(b))
__device__ __forceinline__ unsigned long long dup_f32(float x) {
    unsigned long long r;
    asm("mov.b64 %0, {%1, %1};" : "=l"(r) : "f"(x));
    return r;
}
__device__ __forceinline__ void unpack2(unsigned long long v, float& lo, float& hi) {
    asm("mov.b64 {%0, %1}, %2;" : "=f"(lo), "=f"(hi) : "l"(v));
}

__global__ void __launch_bounds__(256)
gemm_head(const float* __restrict__ A, const float* __restrict__ B,
          float* __restrict__ C, int M)
{
    __shared__ float As[16][128 + 4];
    __shared__ float Bs[16][64];

    const int tid  = threadIdx.x;
    const int row0 = blockIdx.x * 128;
    const int trow = (tid / 16) * 8;
    const int tcol = (tid % 16) * 4;

    unsigned long long acc[8][2];
#pragma unroll
    for (int i = 0; i < 8; i++) acc[i][0] = acc[i][1] = 0ULL;

    for (int k0 = 0; k0 < 128; k0 += 16) {
#pragma unroll
        for (int v = 0; v < 2; v++) {
            int vid = tid + v * 256;
            int r = vid >> 2, k = (vid & 3) * 4;
            float4 t = make_float4(0.f, 0.f, 0.f, 0.f);
            int gr = row0 + r;
            if (gr < M) t = *(const float4*)&A[(size_t)gr * 128 + k0 + k];
            As[k + 0][r] = t.x; As[k + 1][r] = t.y; As[k + 2][r] = t.z; As[k + 3][r] = t.w;
        }
        {
            int bk = tid >> 4, c = (tid & 15) * 4;
            *(float4*)&Bs[bk][c] = *(const float4*)&B[(size_t)(k0 + bk) * 64 + c];
        }
        __syncthreads();
#pragma unroll
        for (int kk = 0; kk < 16; kk++) {
            float a[8];
            *(float4*)&a[0] = *(const float4*)&As[kk][trow];
            *(float4*)&a[4] = *(const float4*)&As[kk][trow + 4];
            float4 b = *(const float4*)&Bs[kk][tcol];
            unsigned long long b01 = ((const unsigned long long*)&b)[0];
            unsigned long long b23 = ((const unsigned long long*)&b)[1];
#pragma unroll
            for (int i = 0; i < 8; i++) {
                unsigned long long aa = dup_f32(a[i]);
                FMA2(acc[i][0], aa, b01);
                FMA2(acc[i][1], aa, b23);
            }
        }
        __syncthreads();
    }
#pragma unroll
    for (int i = 0; i < 8; i++) {
        int gr = row0 + trow + i;
        if (gr >= M) continue;
        float l0, h0, l1, h1;
        unpack2(acc[i][0], l0, h0);
        unpack2(acc[i][1], l1, h1);
        *(float4*)&C[(size_t)gr * 64 + tcol] = make_float4(l0, h0, l1, h1);
    }
}

// ---------------------------------------------------------------------------
// CSR construction (blocked scan)
// ---------------------------------------------------------------------------
__global__ void zero_off_kernel(int* __restrict__ off)
{
    int i = blockIdx.x * blockDim.x + threadIdx.x;
    if (i <= NN) off[i] = 0;
}
__global__ void hist_kernel(const int* __restrict__ ei, int* __restrict__ off)
{
    int e = blockIdx.x * blockDim.x + threadIdx.x;
    if (e >= NE) return;
    atomicAdd(&off[ei[NE + e] + 1], 1);
}

// k1: per-block inclusive scan (coalesced) + block total
__global__ void __launch_bounds__(SCAN_BLK)
scan_blk(int* __restrict__ off, int* __restrict__ bsum)
{
    __shared__ int s[SCAN_BLK];
    const int tid = threadIdx.x;
    const int i = blockIdx.x * SCAN_BLK + tid;
    int v = (i < SCAN_N) ? off[i] : 0;
    s[tid] = v;
    __syncthreads();
#pragma unroll
    for (int d = 1; d < SCAN_BLK; d <<= 1) {
        int t = (tid >= d) ? s[tid - d] : 0;
        __syncthreads();
        s[tid] += t;
        __syncthreads();
    }
    if (i < SCAN_N) off[i] = s[tid];
    if (tid == SCAN_BLK - 1) bsum[blockIdx.x] = s[tid];
}

// k2: exclusive scan of the 98 block sums (single block)
__global__ void __launch_bounds__(128)
scan_bsum(int* __restrict__ bsum)
{
    __shared__ int s[128];
    const int tid = threadIdx.x;
    int v = (tid < SCAN_NB) ? bsum[tid] : 0;
    s[tid] = v;
    __syncthreads();
#pragma unroll
    for (int d = 1; d < 128; d <<= 1) {
        int t = (tid >= d) ? s[tid - d] : 0;
        __syncthreads();
        s[tid] += t;
        __syncthreads();
    }
    if (tid < SCAN_NB) bsum[tid] = s[tid] - v;   // exclusive
}

// k3: add block offsets; also write cur[]
__global__ void __launch_bounds__(SCAN_BLK)
scan_add(int* __restrict__ off, const int* __restrict__ bsum, int* __restrict__ cur)
{
    const int i = blockIdx.x * SCAN_BLK + threadIdx.x;
    if (i < SCAN_N) {
        int v = off[i] + bsum[blockIdx.x];
        off[i] = v;
        if (i < NN) cur[i] = v;
    }
}

__global__ void fill_kernel(const int* __restrict__ ei, int* __restrict__ cur,
                            int* __restrict__ csr)
{
    int e = blockIdx.x * blockDim.x + threadIdx.x;
    if (e >= NE) return;
    int p = atomicAdd(&cur[ei[NE + e]], 1);
    csr[p] = ei[e];
}

// ---------------------------------------------------------------------------
// Aggregates: x[n] = relu(z[n] + sum y[src])   (warp per node, 4-way unroll)
// ---------------------------------------------------------------------------
__device__ __forceinline__ float4 agg_node(const float4* __restrict__ y4,
                                           const float4* __restrict__ z4,
                                           const int* __restrict__ csr,
                                           int node, int lane, int s, int e)
{
    float4 acc = z4[(size_t)node * 32 + lane];
    for (int b = s; b < e; b += 32) {
        int idx = b + lane;
        int mysrc = (idx < e) ? csr[idx] : 0;
        int cnt = e - b; if (cnt > 32) cnt = 32;
        int j = 0;
        for (; j + 4 <= cnt; j += 4) {
            int s0 = __shfl_sync(0xffffffffu, mysrc, j);
            int s1 = __shfl_sync(0xffffffffu, mysrc, j + 1);
            int s2 = __shfl_sync(0xffffffffu, mysrc, j + 2);
            int s3 = __shfl_sync(0xffffffffu, mysrc, j + 3);
            float4 v0 = y4[(size_t)s0 * 32 + lane];
            float4 v1 = y4[(size_t)s1 * 32 + lane];
            float4 v2 = y4[(size_t)s2 * 32 + lane];
            float4 v3 = y4[(size_t)s3 * 32 + lane];
            acc.x += (v0.x + v1.x) + (v2.x + v3.x);
            acc.y += (v0.y + v1.y) + (v2.y + v3.y);
            acc.z += (v0.z + v1.z) + (v2.z + v3.z);
            acc.w += (v0.w + v1.w) + (v2.w + v3.w);
        }
        for (; j < cnt; j++) {
            int s0 = __shfl_sync(0xffffffffu, mysrc, j);
            float4 v0 = y4[(size_t)s0 * 32 + lane];
            acc.x += v0.x; acc.y += v0.y; acc.z += v0.z; acc.w += v0.w;
        }
    }
    acc.x = fmaxf(acc.x, 0.f); acc.y = fmaxf(acc.y, 0.f);
    acc.z = fmaxf(acc.z, 0.f); acc.w = fmaxf(acc.w, 0.f);
    return acc;
}

__global__ void aggregate_split_kernel(const float4* __restrict__ y4,
                                       const float4* __restrict__ z4,
                                       __nv_bfloat16* __restrict__ xh,
                                       __nv_bfloat16* __restrict__ xl,
                                       const int* __restrict__ off,
                                       const int* __restrict__ csr)
{
    int node = (blockIdx.x * blockDim.x + threadIdx.x) >> 5;
    int lane = threadIdx.x & 31;
    if (node >= NN) return;
    float4 acc = agg_node(y4, z4, csr, node, lane, off[node], off[node + 1]);
    __nv_bfloat16 h0, l0, h1, l1, h2, l2, h3, l3;
    split2(acc.x, h0, l0); split2(acc.y, h1, l1);
    split2(acc.z, h2, l2); split2(acc.w, h3, l3);
    __nv_bfloat162 ha, hb, la, lb;
    ha.x = h0; ha.y = h1; hb.x = h2; hb.y = h3;
    la.x = l0; la.y = l1; lb.x = l2; lb.y = l3;
    size_t base = (size_t)node * 128 + lane * 4;
    *(__nv_bfloat162*)(xh + base)     = ha;
    *(__nv_bfloat162*)(xh + base + 2) = hb;
    *(__nv_bfloat162*)(xl + base)     = la;
    *(__nv_bfloat162*)(xl + base + 2) = lb;
}

__global__ void aggregate_f32_kernel(const float4* __restrict__ y4,
                                     const float4* __restrict__ z4,
                                     float4* __restrict__ x4,
                                     const int* __restrict__ off,
                                     const int* __restrict__ csr)
{
    int node = (blockIdx.x * blockDim.x + threadIdx.x) >> 5;
    int lane = threadIdx.x & 31;
    if (node >= NN) return;
    x4[(size_t)node * 32 + lane] =
        agg_node(y4, z4, csr, node, lane, off[node], off[node + 1]);
}

// ---------------------------------------------------------------------------
__global__ void edge_out_kernel(const float* __restrict__ fg,
                                const int* __restrict__ ei,
                                const float* __restrict__ head_b,
                                float* __restrict__ out)
{
    int warp = (blockIdx.x * blockDim.x + threadIdx.x) >> 5;
    int lane = threadIdx.x & 31;
    if (warp >= NE) return;
    int src = ei[warp];
    int dst = ei[NE + warp];
    float v = fg[(size_t)src * 64 + lane] + fg[(size_t)dst * 64 + 32 + lane] + head_b[lane];
    out[(size_t)warp * CLS + lane] = v;
}

// ---------------------------------------------------------------------------
extern "C" void kernel_launch(void* const* d_in, const int* in_sizes, int n_in,
                              void* d_out, int out_size)
{
    const float* obj    = (const float*)d_in[0];
    const int*   ei     = (const int*)d_in[1];   // int32 (JAX x64 disabled)
    const float* emb_w  = (const float*)d_in[2];
    const float* emb_b  = (const float*)d_in[3];
    const float* rel_w  = (const float*)d_in[4];
    const float* rel_b  = (const float*)d_in[5];
    const float* root_w = (const float*)d_in[6];
    const float* head_w = (const float*)d_in[7];
    const float* head_b = (const float*)d_in[8];
    float*       out    = (float*)d_out;

    float *x, *y, *z, *fg, *hw;
    int *off, *cur, *csr, *bsum;
    __nv_bfloat16 *xh, *xl, *ewh, *ewl, *rwh, *rwl, *owh, *owl;
    cudaGetSymbolAddress((void**)&x,    g_x);
    cudaGetSymbolAddress((void**)&y,    g_y);
    cudaGetSymbolAddress((void**)&z,    g_z);
    cudaGetSymbolAddress((void**)&fg,   g_fg);
    cudaGetSymbolAddress((void**)&hw,   g_hw);
    cudaGetSymbolAddress((void**)&off,  g_off);
    cudaGetSymbolAddress((void**)&cur,  g_cur);
    cudaGetSymbolAddress((void**)&csr,  g_csr);
    cudaGetSymbolAddress((void**)&bsum, g_bsum);
    cudaGetSymbolAddress((void**)&xh,   g_xh);
    cudaGetSymbolAddress((void**)&xl,   g_xl);
    cudaGetSymbolAddress((void**)&ewh,  g_ewh);
    cudaGetSymbolAddress((void**)&ewl,  g_ewl);
    cudaGetSymbolAddress((void**)&rwh,  g_rwh);
    cudaGetSymbolAddress((void**)&rwl,  g_rwl);
    cudaGetSymbolAddress((void**)&owh,  g_owh);
    cudaGetSymbolAddress((void**)&owl,  g_owl);

    cudaFuncSetAttribute(gemm_emb,   cudaFuncAttributeMaxDynamicSharedMemorySize, GSM_SIZE);
    cudaFuncSetAttribute(gemm_layer, cudaFuncAttributeMaxDynamicSharedMemorySize, LSM_SIZE);

    // one-time stream/event resources
    static cudaStream_t s_csr = nullptr;
    static cudaEvent_t  ev_fork = nullptr, ev_csr = nullptr;
    if (!s_csr) {
        cudaStreamCreateWithFlags(&s_csr, cudaStreamNonBlocking);
        cudaEventCreateWithFlags(&ev_fork, cudaEventDisableTiming);
        cudaEventCreateWithFlags(&ev_csr,  cudaEventDisableTiming);
    }

    const int gemm_gx   = (NN + 127) / 128;        // 391
    const int ne_blocks = (NE + 255) / 256;
    const int warp_blocks = (NE * 32 + 255) / 256;
    const int agg_blocks  = (NN * 32 + 255) / 256;

    // fork FIRST: CSR chain is independent of everything else
    cudaEventRecord(ev_fork, 0);
    cudaStreamWaitEvent(s_csr, ev_fork, 0);
    zero_off_kernel<<<(NN + 256) / 256, 256, 0, s_csr>>>(off);
    hist_kernel<<<ne_blocks, 256, 0, s_csr>>>(ei, off);
    scan_blk<<<SCAN_NB, SCAN_BLK, 0, s_csr>>>(off, bsum);
    scan_bsum<<<1, 128, 0, s_csr>>>(bsum);
    scan_add<<<SCAN_NB, SCAN_BLK, 0, s_csr>>>(off, bsum, cur);
    fill_kernel<<<ne_blocks, 256, 0, s_csr>>>(ei, cur, csr);
    cudaEventRecord(ev_csr, s_csr);

    // main stream: weight prep -> emb -> layer 0 GEMM
    prep_weights<<<(PW_TOTAL + 255) / 256, 256>>>(
        emb_w, rel_w, root_w, head_w, ewh, ewl, rwh, rwl, owh, owl, hw);

    gemm_emb<<<gemm_gx, 256, GSM_SIZE>>>(obj, ewh, ewl, emb_b, xh, xl);

    gemm_layer<<<gemm_gx, 256, LSM_SIZE>>>(
        xh, xl, rwh, rwl, owh, owl, rel_b, y, z);

    // join: aggregates need CSR
    cudaStreamWaitEvent(0, ev_csr, 0);

    aggregate_split_kernel<<<agg_blocks, 256>>>(
        (const float4*)y, (const float4*)z, xh, xl, off, csr);

    for (int l = 1; l < NLAYERS; l++) {
        gemm_layer<<<gemm_gx, 256, LSM_SIZE>>>(
            xh, xl,
            rwh + (size_t)l * 128 * 128, rwl + (size_t)l * 128 * 128,
            owh + (size_t)l * 128 * 128, owl + (size_t)l * 128 * 128,
            rel_b + (size_t)l * 128, y, z);
        if (l < NLAYERS - 1)
            aggregate_split_kernel<<<agg_blocks, 256>>>(
                (const float4*)y, (const float4*)z, xh, xl, off, csr);
        else
            aggregate_f32_kernel<<<agg_blocks, 256>>>(
                (const float4*)y, (const float4*)z, (float4*)x, off, csr);
    }

    // edge head
    gemm_head<<<gemm_gx, 256>>>(x, hw, fg, NN);
    edge_out_kernel<<<warp_blocks, 256>>>(fg, ei, head_b, out);
}